// round 1
// baseline (speedup 1.0000x reference)
#include <cuda_runtime.h>
#include <cuda_bf16.h>
#include <cstddef>

// Problem constants (fixed by the dataset)
#define N_NODES   100000
#define N_EDGES   1600000
#define DIM       128
#define N_CLASSES 10

#define SCAN_BS   1024
#define SCAN_NB   ((N_NODES + SCAN_BS - 1) / SCAN_BS)   // 98

// ---------------- scratch (static __device__, no allocation) ----------------
__device__ float g_bufA[(size_t)N_NODES * DIM];
__device__ float g_bufB[(size_t)N_NODES * DIM];
__device__ float g_bufT[(size_t)N_NODES * DIM];
__device__ float g_dinv[N_NODES];
__device__ int   g_cnt[N_NODES];          // in-degree incl self-loop
__device__ int   g_off[N_NODES + 1];      // CSR offsets (real edges only)
__device__ int   g_cur[N_NODES];          // scatter cursors / scan temp
__device__ int   g_esrc[N_EDGES];
__device__ float g_enorm[N_EDGES];
__device__ int   g_bsum[SCAN_NB];
__device__ int   g_bpref[SCAN_NB];

// ---------------- degree / norm prep ----------------
__global__ void k_init_deg(int n) {
    int i = blockIdx.x * blockDim.x + threadIdx.x;
    if (i < n) g_cnt[i] = 1;   // self-loop
}

__global__ void k_count_deg(const int* __restrict__ dst, int e) {
    int i = blockIdx.x * blockDim.x + threadIdx.x;
    if (i < e) atomicAdd(&g_cnt[dst[i]], 1);
}

__global__ void k_dinv(int n) {
    int i = blockIdx.x * blockDim.x + threadIdx.x;
    if (i < n) g_dinv[i] = rsqrtf((float)g_cnt[i]);
}

// ---------------- 3-pass exclusive scan of (cnt-1) ----------------
__global__ void k_scan1(int n) {
    __shared__ int sh[SCAN_BS];
    int i = blockIdx.x * SCAN_BS + threadIdx.x;
    int v = (i < n) ? (g_cnt[i] - 1) : 0;
    sh[threadIdx.x] = v;
    __syncthreads();
    for (int ofs = 1; ofs < SCAN_BS; ofs <<= 1) {
        int t = (threadIdx.x >= ofs) ? sh[threadIdx.x - ofs] : 0;
        __syncthreads();
        sh[threadIdx.x] += t;
        __syncthreads();
    }
    if (i < n) g_cur[i] = sh[threadIdx.x];           // partial inclusive
    if (threadIdx.x == SCAN_BS - 1) g_bsum[blockIdx.x] = sh[SCAN_BS - 1];
}

__global__ void k_scan2(int nb) {
    if (threadIdx.x == 0 && blockIdx.x == 0) {
        int s = 0;
        for (int b = 0; b < nb; ++b) { s += g_bsum[b]; g_bpref[b] = s; }
    }
}

__global__ void k_scan3(int n) {
    int i = blockIdx.x * SCAN_BS + threadIdx.x;
    if (i >= n) return;
    int b = blockIdx.x;
    int inc = g_cur[i] + (b > 0 ? g_bpref[b - 1] : 0);
    int c = g_cnt[i] - 1;
    int ex = inc - c;
    g_off[i] = ex;
    g_cur[i] = ex;
    if (i == n - 1) g_off[n] = inc;
}

__global__ void k_scatter(const int* __restrict__ src, const int* __restrict__ dst, int e) {
    int i = blockIdx.x * blockDim.x + threadIdx.x;
    if (i >= e) return;
    int s = src[i], d = dst[i];
    int p = atomicAdd(&g_cur[d], 1);
    g_esrc[p]  = s;
    g_enorm[p] = g_dinv[s] * g_dinv[d];
}

// ---------------- GEMM: C[M,128] = A[M,128] @ W[128,128] (+bias)(+relu) ----------------
// 128x128 tile per block, 256 threads, 8x8 register blocking, K-chunks of 32.
__global__ __launch_bounds__(256) void k_gemm128(
    const float* __restrict__ A, const float* __restrict__ W,
    const float* __restrict__ bias, float* __restrict__ C,
    int M, int has_bias, int do_relu)
{
    __shared__ float sA[128][33];
    __shared__ float sW[32][128];

    int tid = threadIdx.x;
    int tx = tid & 15;            // col group: cols tx*8 .. tx*8+7
    int ty = tid >> 4;            // row group: rows ty*8 .. ty*8+7
    int row0 = blockIdx.x * 128;

    float acc[8][8];
#pragma unroll
    for (int i = 0; i < 8; ++i)
#pragma unroll
        for (int j = 0; j < 8; ++j) acc[i][j] = 0.0f;

    for (int kc = 0; kc < 128; kc += 32) {
        // load A tile (128 rows x 32 k): 1024 float4, 4 per thread
#pragma unroll
        for (int t = 0; t < 4; ++t) {
            int idx4 = tid + t * 256;
            int r  = idx4 >> 3;
            int kk = (idx4 & 7) << 2;
            int gr = row0 + r;
            float4 v = make_float4(0.f, 0.f, 0.f, 0.f);
            if (gr < M) v = *(const float4*)(A + (size_t)gr * 128 + kc + kk);
            sA[r][kk + 0] = v.x; sA[r][kk + 1] = v.y;
            sA[r][kk + 2] = v.z; sA[r][kk + 3] = v.w;
        }
        // load W tile (32 k x 128 cols)
#pragma unroll
        for (int t = 0; t < 4; ++t) {
            int idx4 = tid + t * 256;
            int k = idx4 >> 5;
            int c = (idx4 & 31) << 2;
            *(float4*)&sW[k][c] = *(const float4*)(W + (size_t)(kc + k) * 128 + c);
        }
        __syncthreads();

#pragma unroll
        for (int k = 0; k < 32; ++k) {
            float a[8], b[8];
#pragma unroll
            for (int i = 0; i < 8; ++i) a[i] = sA[ty * 8 + i][k];
#pragma unroll
            for (int j = 0; j < 8; ++j) b[j] = sW[k][tx * 8 + j];
#pragma unroll
            for (int i = 0; i < 8; ++i)
#pragma unroll
                for (int j = 0; j < 8; ++j) acc[i][j] = fmaf(a[i], b[j], acc[i][j]);
        }
        __syncthreads();
    }

#pragma unroll
    for (int i = 0; i < 8; ++i) {
        int gr = row0 + ty * 8 + i;
        if (gr >= M) continue;
#pragma unroll
        for (int j = 0; j < 8; ++j) {
            float v = acc[i][j];
            if (has_bias) v += bias[tx * 8 + j];
            if (do_relu)  v = fmaxf(v, 0.0f);
            acc[i][j] = v;
        }
        float* cp = C + (size_t)gr * 128 + tx * 8;
        *(float4*)(cp + 0) = make_float4(acc[i][0], acc[i][1], acc[i][2], acc[i][3]);
        *(float4*)(cp + 4) = make_float4(acc[i][4], acc[i][5], acc[i][6], acc[i][7]);
    }
}

// ---------------- CSR aggregation: out[i] = dinv[i]^2*t[i] + sum_e norm*t[src] + b; relu ----------------
__global__ __launch_bounds__(128) void k_aggregate(
    const float* __restrict__ t, const float* __restrict__ bias,
    float* __restrict__ out)
{
    int i = blockIdx.x;
    int d = threadIdx.x;     // 0..127
    __shared__ int   s_src[128];
    __shared__ float s_nrm[128];

    float di = g_dinv[i];
    float acc = di * di * t[(size_t)i * 128 + d];

    int e0 = g_off[i], e1 = g_off[i + 1];
    for (int base = e0; base < e1; base += 128) {
        int n = min(128, e1 - base);
        if (d < n) {
            s_src[d] = g_esrc[base + d];
            s_nrm[d] = g_enorm[base + d];
        }
        __syncthreads();
#pragma unroll 4
        for (int k = 0; k < n; ++k)
            acc = fmaf(s_nrm[k], __ldg(&t[(size_t)s_src[k] * 128 + d]), acc);
        __syncthreads();
    }

    acc += bias[d];
    acc = fmaxf(acc, 0.0f);
    out[(size_t)i * 128 + d] = acc;
}

// ---------------- head: out[M,10] = H[M,128] @ W[128,10] + b ----------------
__global__ __launch_bounds__(256) void k_head(
    const float* __restrict__ H, const float* __restrict__ W,
    const float* __restrict__ b, float* __restrict__ out, int M)
{
    __shared__ float sH[64][129];
    __shared__ float sW[128 * N_CLASSES];
    __shared__ float sb[N_CLASSES];

    int tid = threadIdx.x;
    int row0 = blockIdx.x * 64;

    for (int i = tid; i < 128 * N_CLASSES; i += 256) sW[i] = W[i];
    if (tid < N_CLASSES) sb[tid] = b[tid];

#pragma unroll
    for (int t = 0; t < 8; ++t) {
        int idx4 = tid + t * 256;
        int r = idx4 >> 5;
        int c = (idx4 & 31) << 2;
        int gr = row0 + r;
        float4 v = make_float4(0.f, 0.f, 0.f, 0.f);
        if (gr < M) v = *(const float4*)(H + (size_t)gr * 128 + c);
        sH[r][c + 0] = v.x; sH[r][c + 1] = v.y;
        sH[r][c + 2] = v.z; sH[r][c + 3] = v.w;
    }
    __syncthreads();

    for (int o = tid; o < 64 * N_CLASSES; o += 256) {
        int r = o / N_CLASSES, c = o % N_CLASSES;
        int gr = row0 + r;
        if (gr >= M) continue;
        float acc = sb[c];
#pragma unroll
        for (int k = 0; k < 128; ++k)
            acc = fmaf(sH[r][k], sW[k * N_CLASSES + c], acc);
        out[(size_t)gr * N_CLASSES + c] = acc;
    }
}

// ---------------- host launch ----------------
extern "C" void kernel_launch(void* const* d_in, const int* in_sizes, int n_in,
                              void* d_out, int out_size)
{
    const float* x   = (const float*)d_in[0];
    const int*   ei  = (const int*)d_in[1];
    const float* W1  = (const float*)d_in[2];
    const float* b1  = (const float*)d_in[3];
    const float* W2  = (const float*)d_in[4];
    const float* b2  = (const float*)d_in[5];
    const float* W3  = (const float*)d_in[6];
    const float* b3  = (const float*)d_in[7];
    const float* fW1 = (const float*)d_in[8];
    const float* fb1 = (const float*)d_in[9];
    const float* fW2 = (const float*)d_in[10];
    const float* fb2 = (const float*)d_in[11];
    float* out = (float*)d_out;

    int N = in_sizes[0] / DIM;          // 100000
    int E = in_sizes[1] / 2;            // 1600000
    const int* src = ei;
    const int* dst = ei + E;

    float *bufA, *bufB, *bufT;
    cudaGetSymbolAddress((void**)&bufA, g_bufA);
    cudaGetSymbolAddress((void**)&bufB, g_bufB);
    cudaGetSymbolAddress((void**)&bufT, g_bufT);

    int nb256_N = (N + 255) / 256;
    int nb256_E = (E + 255) / 256;
    int nbScan  = (N + SCAN_BS - 1) / SCAN_BS;
    int nbGemm  = (N + 127) / 128;
    int nbHead  = (N + 63) / 64;

    // graph structure prep
    k_init_deg<<<nb256_N, 256>>>(N);
    k_count_deg<<<nb256_E, 256>>>(dst, E);
    k_dinv<<<nb256_N, 256>>>(N);
    k_scan1<<<nbScan, SCAN_BS>>>(N);
    k_scan2<<<1, 32>>>(nbScan);
    k_scan3<<<nbScan, SCAN_BS>>>(N);
    k_scatter<<<nb256_E, 256>>>(src, dst, E);

    // layer 1
    k_gemm128<<<nbGemm, 256>>>(x, W1, nullptr, bufT, N, 0, 0);
    k_aggregate<<<N, 128>>>(bufT, b1, bufA);
    // layer 2
    k_gemm128<<<nbGemm, 256>>>(bufA, W2, nullptr, bufT, N, 0, 0);
    k_aggregate<<<N, 128>>>(bufT, b2, bufB);
    // layer 3
    k_gemm128<<<nbGemm, 256>>>(bufB, W3, nullptr, bufT, N, 0, 0);
    k_aggregate<<<N, 128>>>(bufT, b3, bufA);
    // FFN
    k_gemm128<<<nbGemm, 256>>>(bufA, fW1, fb1, bufT, N, 1, 1);
    k_head<<<nbHead, 256>>>(bufT, fW2, fb2, out, N);
}

// round 3
// speedup vs baseline: 1.3814x; 1.3814x over previous
#include <cuda_runtime.h>
#include <cstdint>
#include <cstddef>

#define N_NODES   100000
#define N_EDGES   1600000
#define DIM       128
#define N_CLASSES 10

#define SCAN_BS   1024
#define SCAN_NB   ((N_NODES + SCAN_BS - 1) / SCAN_BS)

// ---------------- scratch (static __device__, no allocation) ----------------
__device__ float g_bufA[(size_t)N_NODES * DIM];
__device__ float g_bufB[(size_t)N_NODES * DIM];
__device__ float g_bufT[(size_t)N_NODES * DIM];
__device__ float g_dinv[N_NODES];
__device__ int   g_cnt[N_NODES];
__device__ int   g_off[N_NODES + 1];
__device__ int   g_cur[N_NODES];
__device__ int   g_esrc[N_EDGES];
__device__ float g_enorm[N_EDGES];
__device__ int   g_bsum[SCAN_NB];
__device__ int   g_bpref[SCAN_NB];

__device__ __forceinline__ float tf32r(float x) {
    uint32_t u;
    asm("cvt.rna.tf32.f32 %0, %1;" : "=r"(u) : "f"(x));
    return __uint_as_float(u);
}

// ---------------- prep kernels ----------------
__global__ void k_init_deg(int n) {
    int i = blockIdx.x * blockDim.x + threadIdx.x;
    if (i < n) g_cnt[i] = 1;
}
__global__ void k_count_deg(const int* __restrict__ dst, int e) {
    int i = blockIdx.x * blockDim.x + threadIdx.x;
    if (i < e) atomicAdd(&g_cnt[dst[i]], 1);
}
__global__ void k_dinv(int n) {
    int i = blockIdx.x * blockDim.x + threadIdx.x;
    if (i < n) g_dinv[i] = rsqrtf((float)g_cnt[i]);
}
__global__ void k_scan1(int n) {
    __shared__ int sh[SCAN_BS];
    int i = blockIdx.x * SCAN_BS + threadIdx.x;
    int v = (i < n) ? (g_cnt[i] - 1) : 0;
    sh[threadIdx.x] = v;
    __syncthreads();
    for (int ofs = 1; ofs < SCAN_BS; ofs <<= 1) {
        int t = (threadIdx.x >= ofs) ? sh[threadIdx.x - ofs] : 0;
        __syncthreads();
        sh[threadIdx.x] += t;
        __syncthreads();
    }
    if (i < n) g_cur[i] = sh[threadIdx.x];
    if (threadIdx.x == SCAN_BS - 1) g_bsum[blockIdx.x] = sh[SCAN_BS - 1];
}
__global__ void k_scan2(int nb) {
    if (threadIdx.x == 0 && blockIdx.x == 0) {
        int s = 0;
        for (int b = 0; b < nb; ++b) { s += g_bsum[b]; g_bpref[b] = s; }
    }
}
__global__ void k_scan3(int n) {
    int i = blockIdx.x * SCAN_BS + threadIdx.x;
    if (i >= n) return;
    int b = blockIdx.x;
    int inc = g_cur[i] + (b > 0 ? g_bpref[b - 1] : 0);
    int c = g_cnt[i] - 1;
    int ex = inc - c;
    g_off[i] = ex;
    g_cur[i] = ex;
    if (i == n - 1) g_off[n] = inc;
}
__global__ void k_scatter(const int* __restrict__ src, const int* __restrict__ dst, int e) {
    int i = blockIdx.x * blockDim.x + threadIdx.x;
    if (i >= e) return;
    int s = src[i], d = dst[i];
    int p = atomicAdd(&g_cur[d], 1);
    g_esrc[p]  = s;
    g_enorm[p] = g_dinv[s] * g_dinv[d];
}

// ---------------- tf32 mma.sync GEMM: C[M,128] = A[M,128] @ W[128,128] ----------------
// 128x128 tile per CTA, 256 threads = 8 warps (4 M x 2 N), warp tile 32x64.
// mma.m16n8k8: per warp 2 M-frags x 8 N-frags x 16 K-steps.
#define PAD 132   // floats per smem row; (132 mod 32)=4 -> conflict-free frag loads
#define GEMM_SMEM (2 * 128 * PAD * sizeof(float))

__device__ __forceinline__ void mma_tf32(float c[4], const uint32_t a[4],
                                         uint32_t b0, uint32_t b1) {
    asm volatile(
        "mma.sync.aligned.m16n8k8.row.col.f32.tf32.tf32.f32 "
        "{%0,%1,%2,%3}, {%4,%5,%6,%7}, {%8,%9}, {%0,%1,%2,%3};"
        : "+f"(c[0]), "+f"(c[1]), "+f"(c[2]), "+f"(c[3])
        : "r"(a[0]), "r"(a[1]), "r"(a[2]), "r"(a[3]), "r"(b0), "r"(b1));
}

__global__ __launch_bounds__(256) void k_gemm_mma(
    const float* __restrict__ A, const float* __restrict__ W,
    const float* __restrict__ bias, float* __restrict__ C,
    int M, int has_bias, int do_relu)
{
    extern __shared__ float sm[];
    float* sA = sm;                 // [128][PAD]
    float* sW = sm + 128 * PAD;     // [128][PAD]  (W is [k][n] row-major already)

    int tid = threadIdx.x;
    int wid = tid >> 5, lane = tid & 31;
    int gID = lane >> 2, tig = lane & 3;
    int row0 = blockIdx.x * 128;

    // stage A (tf32-rounded)
#pragma unroll
    for (int i = 0; i < 16; ++i) {
        int fid = i * 256 + tid;        // float4 index, 4096 total
        int r = fid >> 5, c4 = (fid & 31) << 2;
        float4 v = make_float4(0.f, 0.f, 0.f, 0.f);
        int gr = row0 + r;
        if (gr < M) v = __ldg((const float4*)(A + (size_t)gr * 128 + c4));
        v.x = tf32r(v.x); v.y = tf32r(v.y); v.z = tf32r(v.z); v.w = tf32r(v.w);
        *(float4*)(sA + r * PAD + c4) = v;
    }
    // stage W (tf32-rounded)
#pragma unroll
    for (int i = 0; i < 16; ++i) {
        int fid = i * 256 + tid;
        int r = fid >> 5, c4 = (fid & 31) << 2;
        float4 v = __ldg((const float4*)(W + (size_t)r * 128 + c4));
        v.x = tf32r(v.x); v.y = tf32r(v.y); v.z = tf32r(v.z); v.w = tf32r(v.w);
        *(float4*)(sW + r * PAD + c4) = v;
    }
    __syncthreads();

    int wm = (wid & 3) * 32;     // warp M origin within tile
    int wn = (wid >> 2) * 64;    // warp N origin

    float acc[2][8][4];
#pragma unroll
    for (int mf = 0; mf < 2; ++mf)
#pragma unroll
        for (int nf = 0; nf < 8; ++nf)
#pragma unroll
            for (int j = 0; j < 4; ++j) acc[mf][nf][j] = 0.f;

#pragma unroll
    for (int k0 = 0; k0 < 128; k0 += 8) {
        uint32_t a[2][4];
#pragma unroll
        for (int mf = 0; mf < 2; ++mf) {
            int mr = wm + mf * 16;
            a[mf][0] = __float_as_uint(sA[(mr + gID)     * PAD + k0 + tig]);
            a[mf][1] = __float_as_uint(sA[(mr + gID + 8) * PAD + k0 + tig]);
            a[mf][2] = __float_as_uint(sA[(mr + gID)     * PAD + k0 + tig + 4]);
            a[mf][3] = __float_as_uint(sA[(mr + gID + 8) * PAD + k0 + tig + 4]);
        }
#pragma unroll
        for (int nf = 0; nf < 8; ++nf) {
            int nc = wn + nf * 8;
            uint32_t b0 = __float_as_uint(sW[(k0 + tig)     * PAD + nc + gID]);
            uint32_t b1 = __float_as_uint(sW[(k0 + tig + 4) * PAD + nc + gID]);
            mma_tf32(acc[0][nf], a[0], b0, b1);
            mma_tf32(acc[1][nf], a[1], b0, b1);
        }
    }

    // epilogue
#pragma unroll
    for (int mf = 0; mf < 2; ++mf) {
        int r_lo = row0 + wm + mf * 16 + gID;
        int r_hi = r_lo + 8;
#pragma unroll
        for (int nf = 0; nf < 8; ++nf) {
            int col = wn + nf * 8 + tig * 2;
            float2 vlo = make_float2(acc[mf][nf][0], acc[mf][nf][1]);
            float2 vhi = make_float2(acc[mf][nf][2], acc[mf][nf][3]);
            if (has_bias) {
                float bx = bias[col], by = bias[col + 1];
                vlo.x += bx; vlo.y += by;
                vhi.x += bx; vhi.y += by;
            }
            if (do_relu) {
                vlo.x = fmaxf(vlo.x, 0.f); vlo.y = fmaxf(vlo.y, 0.f);
                vhi.x = fmaxf(vhi.x, 0.f); vhi.y = fmaxf(vhi.y, 0.f);
            }
            if (r_lo < M) *(float2*)(C + (size_t)r_lo * 128 + col) = vlo;
            if (r_hi < M) *(float2*)(C + (size_t)r_hi * 128 + col) = vhi;
        }
    }
}

// ---------------- CSR aggregation: warp-per-edge, float4 gathers ----------------
__global__ __launch_bounds__(128) void k_aggregate(
    const float* __restrict__ t, const float* __restrict__ bias,
    float* __restrict__ out)
{
    int i = blockIdx.x;
    int tid = threadIdx.x;
    int lane = tid & 31, w = tid >> 5;
    __shared__ float sred[4][128];

    float4 acc = make_float4(0.f, 0.f, 0.f, 0.f);
    int e0 = g_off[i], e1 = g_off[i + 1];
    const float* tcol = t + lane * 4;

    int e = e0 + w;
    for (; e + 12 < e1; e += 16) {
        int s0 = g_esrc[e], s1 = g_esrc[e + 4], s2 = g_esrc[e + 8], s3 = g_esrc[e + 12];
        float n0 = g_enorm[e], n1 = g_enorm[e + 4], n2 = g_enorm[e + 8], n3 = g_enorm[e + 12];
        float4 v0 = __ldg((const float4*)(tcol + (size_t)s0 * 128));
        float4 v1 = __ldg((const float4*)(tcol + (size_t)s1 * 128));
        float4 v2 = __ldg((const float4*)(tcol + (size_t)s2 * 128));
        float4 v3 = __ldg((const float4*)(tcol + (size_t)s3 * 128));
        acc.x = fmaf(n0, v0.x, acc.x); acc.y = fmaf(n0, v0.y, acc.y);
        acc.z = fmaf(n0, v0.z, acc.z); acc.w = fmaf(n0, v0.w, acc.w);
        acc.x = fmaf(n1, v1.x, acc.x); acc.y = fmaf(n1, v1.y, acc.y);
        acc.z = fmaf(n1, v1.z, acc.z); acc.w = fmaf(n1, v1.w, acc.w);
        acc.x = fmaf(n2, v2.x, acc.x); acc.y = fmaf(n2, v2.y, acc.y);
        acc.z = fmaf(n2, v2.z, acc.z); acc.w = fmaf(n2, v2.w, acc.w);
        acc.x = fmaf(n3, v3.x, acc.x); acc.y = fmaf(n3, v3.y, acc.y);
        acc.z = fmaf(n3, v3.z, acc.z); acc.w = fmaf(n3, v3.w, acc.w);
    }
    for (; e < e1; e += 4) {
        int s = g_esrc[e];
        float nm = g_enorm[e];
        float4 v = __ldg((const float4*)(tcol + (size_t)s * 128));
        acc.x = fmaf(nm, v.x, acc.x); acc.y = fmaf(nm, v.y, acc.y);
        acc.z = fmaf(nm, v.z, acc.z); acc.w = fmaf(nm, v.w, acc.w);
    }

    *(float4*)&sred[w][lane * 4] = acc;
    __syncthreads();

    float di = g_dinv[i];
    float v = di * di * t[(size_t)i * 128 + tid]
            + sred[0][tid] + sred[1][tid] + sred[2][tid] + sred[3][tid]
            + bias[tid];
    out[(size_t)i * 128 + tid] = fmaxf(v, 0.f);
}

// ---------------- head: out[M,10] = H[M,128] @ W[128,10] + b ----------------
__global__ __launch_bounds__(256) void k_head(
    const float* __restrict__ H, const float* __restrict__ W,
    const float* __restrict__ b, float* __restrict__ out, int M)
{
    __shared__ float sH[64][129];
    __shared__ float sW[128 * N_CLASSES];
    __shared__ float sb_[N_CLASSES];

    int tid = threadIdx.x;
    int row0 = blockIdx.x * 64;

    for (int i = tid; i < 128 * N_CLASSES; i += 256) sW[i] = W[i];
    if (tid < N_CLASSES) sb_[tid] = b[tid];

#pragma unroll
    for (int t = 0; t < 8; ++t) {
        int idx4 = tid + t * 256;
        int r = idx4 >> 5;
        int c = (idx4 & 31) << 2;
        int gr = row0 + r;
        float4 v = make_float4(0.f, 0.f, 0.f, 0.f);
        if (gr < M) v = *(const float4*)(H + (size_t)gr * 128 + c);
        sH[r][c + 0] = v.x; sH[r][c + 1] = v.y;
        sH[r][c + 2] = v.z; sH[r][c + 3] = v.w;
    }
    __syncthreads();

    for (int o = tid; o < 64 * N_CLASSES; o += 256) {
        int r = o / N_CLASSES, c = o % N_CLASSES;
        int gr = row0 + r;
        if (gr >= M) continue;
        float acc = sb_[c];
#pragma unroll
        for (int k = 0; k < 128; ++k)
            acc = fmaf(sH[r][k], sW[k * N_CLASSES + c], acc);
        out[(size_t)gr * N_CLASSES + c] = acc;
    }
}

// ---------------- host launch ----------------
extern "C" void kernel_launch(void* const* d_in, const int* in_sizes, int n_in,
                              void* d_out, int out_size)
{
    const float* x   = (const float*)d_in[0];
    const int*   ei  = (const int*)d_in[1];
    const float* W1  = (const float*)d_in[2];
    const float* b1  = (const float*)d_in[3];
    const float* W2  = (const float*)d_in[4];
    const float* b2  = (const float*)d_in[5];
    const float* W3  = (const float*)d_in[6];
    const float* b3  = (const float*)d_in[7];
    const float* fW1 = (const float*)d_in[8];
    const float* fb1 = (const float*)d_in[9];
    const float* fW2 = (const float*)d_in[10];
    const float* fb2 = (const float*)d_in[11];
    float* out = (float*)d_out;

    int N = in_sizes[0] / DIM;
    int E = in_sizes[1] / 2;
    const int* src = ei;
    const int* dst = ei + E;

    float *bufA, *bufB, *bufT;
    cudaGetSymbolAddress((void**)&bufA, g_bufA);
    cudaGetSymbolAddress((void**)&bufB, g_bufB);
    cudaGetSymbolAddress((void**)&bufT, g_bufT);

    cudaFuncSetAttribute(k_gemm_mma, cudaFuncAttributeMaxDynamicSharedMemorySize,
                         (int)GEMM_SMEM);

    int nb256_N = (N + 255) / 256;
    int nb256_E = (E + 255) / 256;
    int nbScan  = (N + SCAN_BS - 1) / SCAN_BS;
    int nbGemm  = (N + 127) / 128;
    int nbHead  = (N + 63) / 64;

    // graph structure prep
    k_init_deg<<<nb256_N, 256>>>(N);
    k_count_deg<<<nb256_E, 256>>>(dst, E);
    k_dinv<<<nb256_N, 256>>>(N);
    k_scan1<<<nbScan, SCAN_BS>>>(N);
    k_scan2<<<1, 32>>>(nbScan);
    k_scan3<<<nbScan, SCAN_BS>>>(N);
    k_scatter<<<nb256_E, 256>>>(src, dst, E);

    // layer 1
    k_gemm_mma<<<nbGemm, 256, GEMM_SMEM>>>(x, W1, nullptr, bufT, N, 0, 0);
    k_aggregate<<<N, 128>>>(bufT, b1, bufA);
    // layer 2
    k_gemm_mma<<<nbGemm, 256, GEMM_SMEM>>>(bufA, W2, nullptr, bufT, N, 0, 0);
    k_aggregate<<<N, 128>>>(bufT, b2, bufB);
    // layer 3
    k_gemm_mma<<<nbGemm, 256, GEMM_SMEM>>>(bufB, W3, nullptr, bufT, N, 0, 0);
    k_aggregate<<<N, 128>>>(bufT, b3, bufA);
    // FFN
    k_gemm_mma<<<nbGemm, 256, GEMM_SMEM>>>(bufA, fW1, fb1, bufT, N, 1, 1);
    k_head<<<nbHead, 256>>>(bufT, fW2, fb2, out, N);
}

// round 4
// speedup vs baseline: 1.4558x; 1.0538x over previous
#include <cuda_runtime.h>
#include <cuda_fp16.h>
#include <cstdint>
#include <cstddef>

#define N_NODES   100000
#define N_EDGES   1600000
#define DIM       128
#define N_CLASSES 10

#define SCAN_BS   1024
#define SCAN_NB   ((N_NODES + SCAN_BS - 1) / SCAN_BS)

// ---------------- scratch (static __device__, no allocation) ----------------
__device__ float  g_bufA[(size_t)N_NODES * DIM];   // aggregate outputs (fp32)
__device__ float  g_bufB[(size_t)N_NODES * DIM];
__device__ float  g_bufT[(size_t)N_NODES * DIM];   // FFN hidden (fp32)
__device__ __half g_bufH[(size_t)N_NODES * DIM];   // GEMM output h (fp16, gather target)
__device__ float  g_dinv[N_NODES];
__device__ int    g_cnt[N_NODES];
__device__ int    g_off[N_NODES + 1];
__device__ int    g_cur[N_NODES];
__device__ int    g_esrc[N_EDGES];
__device__ float  g_enorm[N_EDGES];
__device__ int    g_bsum[SCAN_NB];
__device__ int    g_bpref[SCAN_NB];

__device__ __forceinline__ float tf32r(float x) {
    uint32_t u;
    asm("cvt.rna.tf32.f32 %0, %1;" : "=r"(u) : "f"(x));
    return __uint_as_float(u);
}

// ---------------- prep kernels ----------------
__global__ void k_init_deg(int n) {
    int i = blockIdx.x * blockDim.x + threadIdx.x;
    if (i < n) g_cnt[i] = 1;
}
__global__ void k_count_deg(const int* __restrict__ dst, int e) {
    int i = blockIdx.x * blockDim.x + threadIdx.x;
    if (i < e) atomicAdd(&g_cnt[dst[i]], 1);
}
__global__ void k_dinv(int n) {
    int i = blockIdx.x * blockDim.x + threadIdx.x;
    if (i < n) g_dinv[i] = rsqrtf((float)g_cnt[i]);
}
__global__ void k_scan1(int n) {
    __shared__ int sh[SCAN_BS];
    int i = blockIdx.x * SCAN_BS + threadIdx.x;
    int v = (i < n) ? (g_cnt[i] - 1) : 0;
    sh[threadIdx.x] = v;
    __syncthreads();
    for (int ofs = 1; ofs < SCAN_BS; ofs <<= 1) {
        int t = (threadIdx.x >= ofs) ? sh[threadIdx.x - ofs] : 0;
        __syncthreads();
        sh[threadIdx.x] += t;
        __syncthreads();
    }
    if (i < n) g_cur[i] = sh[threadIdx.x];
    if (threadIdx.x == SCAN_BS - 1) g_bsum[blockIdx.x] = sh[SCAN_BS - 1];
}
__global__ void k_scan2(int nb) {
    if (threadIdx.x == 0 && blockIdx.x == 0) {
        int s = 0;
        for (int b = 0; b < nb; ++b) { s += g_bsum[b]; g_bpref[b] = s; }
    }
}
__global__ void k_scan3(int n) {
    int i = blockIdx.x * SCAN_BS + threadIdx.x;
    if (i >= n) return;
    int b = blockIdx.x;
    int inc = g_cur[i] + (b > 0 ? g_bpref[b - 1] : 0);
    int c = g_cnt[i] - 1;
    int ex = inc - c;
    g_off[i] = ex;
    g_cur[i] = ex;
    if (i == n - 1) g_off[n] = inc;
}
__global__ void k_scatter(const int* __restrict__ src, const int* __restrict__ dst, int e) {
    int i = blockIdx.x * blockDim.x + threadIdx.x;
    if (i >= e) return;
    int s = src[i], d = dst[i];
    int p = atomicAdd(&g_cur[d], 1);
    g_esrc[p]  = s;
    g_enorm[p] = g_dinv[s] * g_dinv[d];
}

// ---------------- tf32 mma.sync GEMM: C[M,128] = A[M,128] @ W[128,128] ----------------
// 128x128 tile per CTA, 256 threads = 8 warps (4 M x 2 N), warp tile 32x64.
#define PAD 132
#define GEMM_SMEM (2 * 128 * PAD * sizeof(float))

__device__ __forceinline__ void mma_tf32(float c[4], const uint32_t a[4],
                                         uint32_t b0, uint32_t b1) {
    asm volatile(
        "mma.sync.aligned.m16n8k8.row.col.f32.tf32.tf32.f32 "
        "{%0,%1,%2,%3}, {%4,%5,%6,%7}, {%8,%9}, {%0,%1,%2,%3};"
        : "+f"(c[0]), "+f"(c[1]), "+f"(c[2]), "+f"(c[3])
        : "r"(a[0]), "r"(a[1]), "r"(a[2]), "r"(a[3]), "r"(b0), "r"(b1));
}

// out_mode: 0 -> fp32 to C32; 1 -> fp16 to C16
__global__ __launch_bounds__(256) void k_gemm_mma(
    const float* __restrict__ A, const float* __restrict__ W,
    const float* __restrict__ bias, float* __restrict__ C32,
    __half* __restrict__ C16,
    int M, int has_bias, int do_relu, int out_half)
{
    extern __shared__ float sm[];
    float* sA = sm;
    float* sW = sm + 128 * PAD;

    int tid = threadIdx.x;
    int wid = tid >> 5, lane = tid & 31;
    int gID = lane >> 2, tig = lane & 3;
    int row0 = blockIdx.x * 128;

#pragma unroll
    for (int i = 0; i < 16; ++i) {
        int fid = i * 256 + tid;
        int r = fid >> 5, c4 = (fid & 31) << 2;
        float4 v = make_float4(0.f, 0.f, 0.f, 0.f);
        int gr = row0 + r;
        if (gr < M) v = __ldg((const float4*)(A + (size_t)gr * 128 + c4));
        v.x = tf32r(v.x); v.y = tf32r(v.y); v.z = tf32r(v.z); v.w = tf32r(v.w);
        *(float4*)(sA + r * PAD + c4) = v;
    }
#pragma unroll
    for (int i = 0; i < 16; ++i) {
        int fid = i * 256 + tid;
        int r = fid >> 5, c4 = (fid & 31) << 2;
        float4 v = __ldg((const float4*)(W + (size_t)r * 128 + c4));
        v.x = tf32r(v.x); v.y = tf32r(v.y); v.z = tf32r(v.z); v.w = tf32r(v.w);
        *(float4*)(sW + r * PAD + c4) = v;
    }
    __syncthreads();

    int wm = (wid & 3) * 32;
    int wn = (wid >> 2) * 64;

    float acc[2][8][4];
#pragma unroll
    for (int mf = 0; mf < 2; ++mf)
#pragma unroll
        for (int nf = 0; nf < 8; ++nf)
#pragma unroll
            for (int j = 0; j < 4; ++j) acc[mf][nf][j] = 0.f;

#pragma unroll
    for (int k0 = 0; k0 < 128; k0 += 8) {
        uint32_t a[2][4];
#pragma unroll
        for (int mf = 0; mf < 2; ++mf) {
            int mr = wm + mf * 16;
            a[mf][0] = __float_as_uint(sA[(mr + gID)     * PAD + k0 + tig]);
            a[mf][1] = __float_as_uint(sA[(mr + gID + 8) * PAD + k0 + tig]);
            a[mf][2] = __float_as_uint(sA[(mr + gID)     * PAD + k0 + tig + 4]);
            a[mf][3] = __float_as_uint(sA[(mr + gID + 8) * PAD + k0 + tig + 4]);
        }
#pragma unroll
        for (int nf = 0; nf < 8; ++nf) {
            int nc = wn + nf * 8;
            uint32_t b0 = __float_as_uint(sW[(k0 + tig)     * PAD + nc + gID]);
            uint32_t b1 = __float_as_uint(sW[(k0 + tig + 4) * PAD + nc + gID]);
            mma_tf32(acc[0][nf], a[0], b0, b1);
            mma_tf32(acc[1][nf], a[1], b0, b1);
        }
    }

#pragma unroll
    for (int mf = 0; mf < 2; ++mf) {
        int r_lo = row0 + wm + mf * 16 + gID;
        int r_hi = r_lo + 8;
#pragma unroll
        for (int nf = 0; nf < 8; ++nf) {
            int col = wn + nf * 8 + tig * 2;
            float2 vlo = make_float2(acc[mf][nf][0], acc[mf][nf][1]);
            float2 vhi = make_float2(acc[mf][nf][2], acc[mf][nf][3]);
            if (has_bias) {
                float bx = bias[col], by = bias[col + 1];
                vlo.x += bx; vlo.y += by;
                vhi.x += bx; vhi.y += by;
            }
            if (do_relu) {
                vlo.x = fmaxf(vlo.x, 0.f); vlo.y = fmaxf(vlo.y, 0.f);
                vhi.x = fmaxf(vhi.x, 0.f); vhi.y = fmaxf(vhi.y, 0.f);
            }
            if (out_half) {
                if (r_lo < M) *(__half2*)(C16 + (size_t)r_lo * 128 + col) = __float22half2_rn(vlo);
                if (r_hi < M) *(__half2*)(C16 + (size_t)r_hi * 128 + col) = __float22half2_rn(vhi);
            } else {
                if (r_lo < M) *(float2*)(C32 + (size_t)r_lo * 128 + col) = vlo;
                if (r_hi < M) *(float2*)(C32 + (size_t)r_hi * 128 + col) = vhi;
            }
        }
    }
}

// ---------------- CSR aggregation over fp16 h: out = self + sum norm*h[src] + b; relu ----------------
// 128 threads/node; warp w handles edges e0+w, stride 4; each lane loads 4 halves (8B).
__global__ __launch_bounds__(128) void k_aggregate(
    const __half* __restrict__ h, const float* __restrict__ bias,
    float* __restrict__ out)
{
    int i = blockIdx.x;
    int tid = threadIdx.x;
    int lane = tid & 31, w = tid >> 5;
    __shared__ float sred[4][128];

    float4 acc = make_float4(0.f, 0.f, 0.f, 0.f);
    int e0 = g_off[i], e1 = g_off[i + 1];
    const __half* hcol = h + lane * 4;

    int e = e0 + w;
    for (; e + 12 < e1; e += 16) {
        int s0 = g_esrc[e], s1 = g_esrc[e + 4], s2 = g_esrc[e + 8], s3 = g_esrc[e + 12];
        float n0 = g_enorm[e], n1 = g_enorm[e + 4], n2 = g_enorm[e + 8], n3 = g_enorm[e + 12];
        uint2 u0 = __ldg((const uint2*)(hcol + (size_t)s0 * 128));
        uint2 u1 = __ldg((const uint2*)(hcol + (size_t)s1 * 128));
        uint2 u2 = __ldg((const uint2*)(hcol + (size_t)s2 * 128));
        uint2 u3 = __ldg((const uint2*)(hcol + (size_t)s3 * 128));
        float2 a0 = __half22float2(*(const __half2*)&u0.x), b0 = __half22float2(*(const __half2*)&u0.y);
        float2 a1 = __half22float2(*(const __half2*)&u1.x), b1 = __half22float2(*(const __half2*)&u1.y);
        float2 a2 = __half22float2(*(const __half2*)&u2.x), b2 = __half22float2(*(const __half2*)&u2.y);
        float2 a3 = __half22float2(*(const __half2*)&u3.x), b3 = __half22float2(*(const __half2*)&u3.y);
        acc.x = fmaf(n0, a0.x, acc.x); acc.y = fmaf(n0, a0.y, acc.y);
        acc.z = fmaf(n0, b0.x, acc.z); acc.w = fmaf(n0, b0.y, acc.w);
        acc.x = fmaf(n1, a1.x, acc.x); acc.y = fmaf(n1, a1.y, acc.y);
        acc.z = fmaf(n1, b1.x, acc.z); acc.w = fmaf(n1, b1.y, acc.w);
        acc.x = fmaf(n2, a2.x, acc.x); acc.y = fmaf(n2, a2.y, acc.y);
        acc.z = fmaf(n2, b2.x, acc.z); acc.w = fmaf(n2, b2.y, acc.w);
        acc.x = fmaf(n3, a3.x, acc.x); acc.y = fmaf(n3, a3.y, acc.y);
        acc.z = fmaf(n3, b3.x, acc.z); acc.w = fmaf(n3, b3.y, acc.w);
    }
    for (; e < e1; e += 4) {
        int s = g_esrc[e];
        float nm = g_enorm[e];
        uint2 u = __ldg((const uint2*)(hcol + (size_t)s * 128));
        float2 a = __half22float2(*(const __half2*)&u.x), b = __half22float2(*(const __half2*)&u.y);
        acc.x = fmaf(nm, a.x, acc.x); acc.y = fmaf(nm, a.y, acc.y);
        acc.z = fmaf(nm, b.x, acc.z); acc.w = fmaf(nm, b.y, acc.w);
    }

    *(float4*)&sred[w][lane * 4] = acc;
    __syncthreads();

    float di = g_dinv[i];
    float self = __half2float(h[(size_t)i * 128 + tid]);
    float v = di * di * self
            + sred[0][tid] + sred[1][tid] + sred[2][tid] + sred[3][tid]
            + bias[tid];
    out[(size_t)i * 128 + tid] = fmaxf(v, 0.f);
}

// ---------------- head: out[M,10] = H[M,128] @ W[128,10] + b ----------------
__global__ __launch_bounds__(256) void k_head(
    const float* __restrict__ H, const float* __restrict__ W,
    const float* __restrict__ b, float* __restrict__ out, int M)
{
    __shared__ float sH[64][129];
    __shared__ float sW[128 * N_CLASSES];
    __shared__ float sb_[N_CLASSES];

    int tid = threadIdx.x;
    int row0 = blockIdx.x * 64;

    for (int i = tid; i < 128 * N_CLASSES; i += 256) sW[i] = W[i];
    if (tid < N_CLASSES) sb_[tid] = b[tid];

#pragma unroll
    for (int t = 0; t < 8; ++t) {
        int idx4 = tid + t * 256;
        int r = idx4 >> 5;
        int c = (idx4 & 31) << 2;
        int gr = row0 + r;
        float4 v = make_float4(0.f, 0.f, 0.f, 0.f);
        if (gr < M) v = *(const float4*)(H + (size_t)gr * 128 + c);
        sH[r][c + 0] = v.x; sH[r][c + 1] = v.y;
        sH[r][c + 2] = v.z; sH[r][c + 3] = v.w;
    }
    __syncthreads();

    for (int o = tid; o < 64 * N_CLASSES; o += 256) {
        int r = o / N_CLASSES, c = o % N_CLASSES;
        int gr = row0 + r;
        if (gr >= M) continue;
        float acc = sb_[c];
#pragma unroll
        for (int k = 0; k < 128; ++k)
            acc = fmaf(sH[r][k], sW[k * N_CLASSES + c], acc);
        out[(size_t)gr * N_CLASSES + c] = acc;
    }
}

// ---------------- host launch ----------------
extern "C" void kernel_launch(void* const* d_in, const int* in_sizes, int n_in,
                              void* d_out, int out_size)
{
    const float* x   = (const float*)d_in[0];
    const int*   ei  = (const int*)d_in[1];
    const float* W1  = (const float*)d_in[2];
    const float* b1  = (const float*)d_in[3];
    const float* W2  = (const float*)d_in[4];
    const float* b2  = (const float*)d_in[5];
    const float* W3  = (const float*)d_in[6];
    const float* b3  = (const float*)d_in[7];
    const float* fW1 = (const float*)d_in[8];
    const float* fb1 = (const float*)d_in[9];
    const float* fW2 = (const float*)d_in[10];
    const float* fb2 = (const float*)d_in[11];
    float* out = (float*)d_out;

    int N = in_sizes[0] / DIM;
    int E = in_sizes[1] / 2;
    const int* src = ei;
    const int* dst = ei + E;

    float *bufA, *bufB, *bufT;
    __half* bufH;
    cudaGetSymbolAddress((void**)&bufA, g_bufA);
    cudaGetSymbolAddress((void**)&bufB, g_bufB);
    cudaGetSymbolAddress((void**)&bufT, g_bufT);
    cudaGetSymbolAddress((void**)&bufH, g_bufH);

    cudaFuncSetAttribute(k_gemm_mma, cudaFuncAttributeMaxDynamicSharedMemorySize,
                         (int)GEMM_SMEM);

    int nb256_N = (N + 255) / 256;
    int nb256_E = (E + 255) / 256;
    int nbScan  = (N + SCAN_BS - 1) / SCAN_BS;
    int nbGemm  = (N + 127) / 128;
    int nbHead  = (N + 63) / 64;

    // graph structure prep
    k_init_deg<<<nb256_N, 256>>>(N);
    k_count_deg<<<nb256_E, 256>>>(dst, E);
    k_dinv<<<nb256_N, 256>>>(N);
    k_scan1<<<nbScan, SCAN_BS>>>(N);
    k_scan2<<<1, 32>>>(nbScan);
    k_scan3<<<nbScan, SCAN_BS>>>(N);
    k_scatter<<<nb256_E, 256>>>(src, dst, E);

    // layer 1
    k_gemm_mma<<<nbGemm, 256, GEMM_SMEM>>>(x, W1, nullptr, nullptr, bufH, N, 0, 0, 1);
    k_aggregate<<<N, 128>>>(bufH, b1, bufA);
    // layer 2
    k_gemm_mma<<<nbGemm, 256, GEMM_SMEM>>>(bufA, W2, nullptr, nullptr, bufH, N, 0, 0, 1);
    k_aggregate<<<N, 128>>>(bufH, b2, bufB);
    // layer 3
    k_gemm_mma<<<nbGemm, 256, GEMM_SMEM>>>(bufB, W3, nullptr, nullptr, bufH, N, 0, 0, 1);
    k_aggregate<<<N, 128>>>(bufH, b3, bufA);
    // FFN
    k_gemm_mma<<<nbGemm, 256, GEMM_SMEM>>>(bufA, fW1, fb1, bufT, nullptr, N, 1, 1, 0);
    k_head<<<nbHead, 256>>>(bufT, fW2, fb2, out, N);
}

// round 5
// speedup vs baseline: 1.8832x; 1.2936x over previous
#include <cuda_runtime.h>
#include <cuda_fp16.h>
#include <cstdint>
#include <cstddef>

#define N_NODES   100000
#define N_EDGES   1600000
#define DIM       128
#define N_CLASSES 10

#define SCAN_BS   1024
#define SCAN_NB   ((N_NODES + SCAN_BS - 1) / SCAN_BS)

// ---------------- scratch (static __device__, no allocation) ----------------
__device__ float  g_bufA[(size_t)N_NODES * DIM];   // aggregate outputs (fp32)
__device__ float  g_bufB[(size_t)N_NODES * DIM];
__device__ float  g_bufT[(size_t)N_NODES * DIM];   // FFN hidden (fp32)
__device__ __half g_bufH[(size_t)N_NODES * DIM];   // GEMM output h (fp16, gather target)
__device__ float  g_dinv[N_NODES];
__device__ int    g_cnt[N_NODES];
__device__ int    g_off[N_NODES + 1];
__device__ int    g_cur[N_NODES];
__device__ int2   g_edge[N_EDGES];                 // (src, norm bits)
__device__ int    g_bsum[SCAN_NB];
__device__ int    g_bpref[SCAN_NB];

__device__ __forceinline__ float tf32r(float x) {
    uint32_t u;
    asm("cvt.rna.tf32.f32 %0, %1;" : "=r"(u) : "f"(x));
    return __uint_as_float(u);
}

// ---------------- prep kernels ----------------
__global__ void k_init_deg(int n) {
    int i = blockIdx.x * blockDim.x + threadIdx.x;
    if (i < n) g_cnt[i] = 1;
}
__global__ void k_count_deg(const int* __restrict__ dst, int e) {
    int i = blockIdx.x * blockDim.x + threadIdx.x;
    if (i < e) atomicAdd(&g_cnt[dst[i]], 1);
}
__global__ void k_dinv(int n) {
    int i = blockIdx.x * blockDim.x + threadIdx.x;
    if (i < n) g_dinv[i] = rsqrtf((float)g_cnt[i]);
}
__global__ void k_scan1(int n) {
    __shared__ int sh[SCAN_BS];
    int i = blockIdx.x * SCAN_BS + threadIdx.x;
    int v = (i < n) ? (g_cnt[i] - 1) : 0;
    sh[threadIdx.x] = v;
    __syncthreads();
    for (int ofs = 1; ofs < SCAN_BS; ofs <<= 1) {
        int t = (threadIdx.x >= ofs) ? sh[threadIdx.x - ofs] : 0;
        __syncthreads();
        sh[threadIdx.x] += t;
        __syncthreads();
    }
    if (i < n) g_cur[i] = sh[threadIdx.x];
    if (threadIdx.x == SCAN_BS - 1) g_bsum[blockIdx.x] = sh[SCAN_BS - 1];
}
__global__ void k_scan2(int nb) {
    if (threadIdx.x == 0 && blockIdx.x == 0) {
        int s = 0;
        for (int b = 0; b < nb; ++b) { s += g_bsum[b]; g_bpref[b] = s; }
    }
}
__global__ void k_scan3(int n) {
    int i = blockIdx.x * SCAN_BS + threadIdx.x;
    if (i >= n) return;
    int b = blockIdx.x;
    int inc = g_cur[i] + (b > 0 ? g_bpref[b - 1] : 0);
    int c = g_cnt[i] - 1;
    int ex = inc - c;
    g_off[i] = ex;
    g_cur[i] = ex;
    if (i == n - 1) g_off[n] = inc;
}
__global__ void k_scatter(const int* __restrict__ src, const int* __restrict__ dst, int e) {
    int i = blockIdx.x * blockDim.x + threadIdx.x;
    if (i >= e) return;
    int s = src[i], d = dst[i];
    int p = atomicAdd(&g_cur[d], 1);
    float nm = g_dinv[s] * g_dinv[d];
    g_edge[p] = make_int2(s, __float_as_int(nm));
}

// ---------------- tf32 mma.sync GEMM: C[M,128] = A[M,128] @ W[128,128] ----------------
#define PAD 132
#define GEMM_SMEM (2 * 128 * PAD * sizeof(float))

__device__ __forceinline__ void mma_tf32(float c[4], const uint32_t a[4],
                                         uint32_t b0, uint32_t b1) {
    asm volatile(
        "mma.sync.aligned.m16n8k8.row.col.f32.tf32.tf32.f32 "
        "{%0,%1,%2,%3}, {%4,%5,%6,%7}, {%8,%9}, {%0,%1,%2,%3};"
        : "+f"(c[0]), "+f"(c[1]), "+f"(c[2]), "+f"(c[3])
        : "r"(a[0]), "r"(a[1]), "r"(a[2]), "r"(a[3]), "r"(b0), "r"(b1));
}

__global__ __launch_bounds__(256) void k_gemm_mma(
    const float* __restrict__ A, const float* __restrict__ W,
    const float* __restrict__ bias, float* __restrict__ C32,
    __half* __restrict__ C16,
    int M, int has_bias, int do_relu, int out_half)
{
    extern __shared__ float sm[];
    float* sA = sm;
    float* sW = sm + 128 * PAD;

    int tid = threadIdx.x;
    int wid = tid >> 5, lane = tid & 31;
    int gID = lane >> 2, tig = lane & 3;
    int row0 = blockIdx.x * 128;

#pragma unroll
    for (int i = 0; i < 16; ++i) {
        int fid = i * 256 + tid;
        int r = fid >> 5, c4 = (fid & 31) << 2;
        float4 v = make_float4(0.f, 0.f, 0.f, 0.f);
        int gr = row0 + r;
        if (gr < M) v = __ldg((const float4*)(A + (size_t)gr * 128 + c4));
        v.x = tf32r(v.x); v.y = tf32r(v.y); v.z = tf32r(v.z); v.w = tf32r(v.w);
        *(float4*)(sA + r * PAD + c4) = v;
    }
#pragma unroll
    for (int i = 0; i < 16; ++i) {
        int fid = i * 256 + tid;
        int r = fid >> 5, c4 = (fid & 31) << 2;
        float4 v = __ldg((const float4*)(W + (size_t)r * 128 + c4));
        v.x = tf32r(v.x); v.y = tf32r(v.y); v.z = tf32r(v.z); v.w = tf32r(v.w);
        *(float4*)(sW + r * PAD + c4) = v;
    }
    __syncthreads();

    int wm = (wid & 3) * 32;
    int wn = (wid >> 2) * 64;

    float acc[2][8][4];
#pragma unroll
    for (int mf = 0; mf < 2; ++mf)
#pragma unroll
        for (int nf = 0; nf < 8; ++nf)
#pragma unroll
            for (int j = 0; j < 4; ++j) acc[mf][nf][j] = 0.f;

#pragma unroll
    for (int k0 = 0; k0 < 128; k0 += 8) {
        uint32_t a[2][4];
#pragma unroll
        for (int mf = 0; mf < 2; ++mf) {
            int mr = wm + mf * 16;
            a[mf][0] = __float_as_uint(sA[(mr + gID)     * PAD + k0 + tig]);
            a[mf][1] = __float_as_uint(sA[(mr + gID + 8) * PAD + k0 + tig]);
            a[mf][2] = __float_as_uint(sA[(mr + gID)     * PAD + k0 + tig + 4]);
            a[mf][3] = __float_as_uint(sA[(mr + gID + 8) * PAD + k0 + tig + 4]);
        }
#pragma unroll
        for (int nf = 0; nf < 8; ++nf) {
            int nc = wn + nf * 8;
            uint32_t b0 = __float_as_uint(sW[(k0 + tig)     * PAD + nc + gID]);
            uint32_t b1 = __float_as_uint(sW[(k0 + tig + 4) * PAD + nc + gID]);
            mma_tf32(acc[0][nf], a[0], b0, b1);
            mma_tf32(acc[1][nf], a[1], b0, b1);
        }
    }

#pragma unroll
    for (int mf = 0; mf < 2; ++mf) {
        int r_lo = row0 + wm + mf * 16 + gID;
        int r_hi = r_lo + 8;
#pragma unroll
        for (int nf = 0; nf < 8; ++nf) {
            int col = wn + nf * 8 + tig * 2;
            float2 vlo = make_float2(acc[mf][nf][0], acc[mf][nf][1]);
            float2 vhi = make_float2(acc[mf][nf][2], acc[mf][nf][3]);
            if (has_bias) {
                float bx = bias[col], by = bias[col + 1];
                vlo.x += bx; vlo.y += by;
                vhi.x += bx; vhi.y += by;
            }
            if (do_relu) {
                vlo.x = fmaxf(vlo.x, 0.f); vlo.y = fmaxf(vlo.y, 0.f);
                vhi.x = fmaxf(vhi.x, 0.f); vhi.y = fmaxf(vhi.y, 0.f);
            }
            if (out_half) {
                if (r_lo < M) *(__half2*)(C16 + (size_t)r_lo * 128 + col) = __float22half2_rn(vlo);
                if (r_hi < M) *(__half2*)(C16 + (size_t)r_hi * 128 + col) = __float22half2_rn(vhi);
            } else {
                if (r_lo < M) *(float2*)(C32 + (size_t)r_lo * 128 + col) = vlo;
                if (r_hi < M) *(float2*)(C32 + (size_t)r_hi * 128 + col) = vhi;
            }
        }
    }
}

// ---------------- CSR aggregation: one warp per node, 8-deep edge unroll ----------------
// 256 threads = 8 warps = 8 nodes/CTA. Lane owns 4 features (8B fp16).
__global__ __launch_bounds__(256) void k_aggregate(
    const __half* __restrict__ h, const float* __restrict__ bias,
    float* __restrict__ out, int N)
{
    int warp = (blockIdx.x << 3) + (threadIdx.x >> 5);
    if (warp >= N) return;
    int i = warp;
    int lane = threadIdx.x & 31;

    const __half* hcol = h + lane * 4;
    float4 acc = make_float4(0.f, 0.f, 0.f, 0.f);

    int e0 = g_off[i], e1 = g_off[i + 1];
    for (int e = e0; e < e1; e += 8) {
        int n = e1 - e;
        int2 rec[8];
        uint2 hv[8];
#pragma unroll
        for (int j = 0; j < 8; ++j)
            if (j < n) rec[j] = __ldg(&g_edge[e + j]);
#pragma unroll
        for (int j = 0; j < 8; ++j)
            if (j < n) hv[j] = __ldg((const uint2*)(hcol + (size_t)rec[j].x * 128));
#pragma unroll
        for (int j = 0; j < 8; ++j) {
            if (j < n) {
                float nm = __int_as_float(rec[j].y);
                float2 a = __half22float2(*(const __half2*)&hv[j].x);
                float2 b = __half22float2(*(const __half2*)&hv[j].y);
                acc.x = fmaf(nm, a.x, acc.x); acc.y = fmaf(nm, a.y, acc.y);
                acc.z = fmaf(nm, b.x, acc.z); acc.w = fmaf(nm, b.y, acc.w);
            }
        }
    }

    // self-loop term + bias + relu
    float di = g_dinv[i];
    float dii = di * di;
    uint2 us = __ldg((const uint2*)(hcol + (size_t)i * 128));
    float2 sa = __half22float2(*(const __half2*)&us.x);
    float2 sb = __half22float2(*(const __half2*)&us.y);
    float4 bv = __ldg((const float4*)(bias + lane * 4));
    acc.x = fmaf(dii, sa.x, acc.x) + bv.x;
    acc.y = fmaf(dii, sa.y, acc.y) + bv.y;
    acc.z = fmaf(dii, sb.x, acc.z) + bv.z;
    acc.w = fmaf(dii, sb.y, acc.w) + bv.w;
    acc.x = fmaxf(acc.x, 0.f); acc.y = fmaxf(acc.y, 0.f);
    acc.z = fmaxf(acc.z, 0.f); acc.w = fmaxf(acc.w, 0.f);
    *(float4*)(out + (size_t)i * 128 + lane * 4) = acc;
}

// ---------------- head: out[M,10] = H[M,128] @ W[128,10] + b ----------------
__global__ __launch_bounds__(256) void k_head(
    const float* __restrict__ H, const float* __restrict__ W,
    const float* __restrict__ b, float* __restrict__ out, int M)
{
    __shared__ float sH[64][129];
    __shared__ float sW[128 * N_CLASSES];
    __shared__ float sb_[N_CLASSES];

    int tid = threadIdx.x;
    int row0 = blockIdx.x * 64;

    for (int i = tid; i < 128 * N_CLASSES; i += 256) sW[i] = W[i];
    if (tid < N_CLASSES) sb_[tid] = b[tid];

#pragma unroll
    for (int t = 0; t < 8; ++t) {
        int idx4 = tid + t * 256;
        int r = idx4 >> 5;
        int c = (idx4 & 31) << 2;
        int gr = row0 + r;
        float4 v = make_float4(0.f, 0.f, 0.f, 0.f);
        if (gr < M) v = *(const float4*)(H + (size_t)gr * 128 + c);
        sH[r][c + 0] = v.x; sH[r][c + 1] = v.y;
        sH[r][c + 2] = v.z; sH[r][c + 3] = v.w;
    }
    __syncthreads();

    for (int o = tid; o < 64 * N_CLASSES; o += 256) {
        int r = o / N_CLASSES, c = o % N_CLASSES;
        int gr = row0 + r;
        if (gr >= M) continue;
        float acc = sb_[c];
#pragma unroll
        for (int k = 0; k < 128; ++k)
            acc = fmaf(sH[r][k], sW[k * N_CLASSES + c], acc);
        out[(size_t)gr * N_CLASSES + c] = acc;
    }
}

// ---------------- host launch ----------------
extern "C" void kernel_launch(void* const* d_in, const int* in_sizes, int n_in,
                              void* d_out, int out_size)
{
    const float* x   = (const float*)d_in[0];
    const int*   ei  = (const int*)d_in[1];
    const float* W1  = (const float*)d_in[2];
    const float* b1  = (const float*)d_in[3];
    const float* W2  = (const float*)d_in[4];
    const float* b2  = (const float*)d_in[5];
    const float* W3  = (const float*)d_in[6];
    const float* b3  = (const float*)d_in[7];
    const float* fW1 = (const float*)d_in[8];
    const float* fb1 = (const float*)d_in[9];
    const float* fW2 = (const float*)d_in[10];
    const float* fb2 = (const float*)d_in[11];
    float* out = (float*)d_out;

    int N = in_sizes[0] / DIM;
    int E = in_sizes[1] / 2;
    const int* src = ei;
    const int* dst = ei + E;

    float *bufA, *bufB, *bufT;
    __half* bufH;
    cudaGetSymbolAddress((void**)&bufA, g_bufA);
    cudaGetSymbolAddress((void**)&bufB, g_bufB);
    cudaGetSymbolAddress((void**)&bufT, g_bufT);
    cudaGetSymbolAddress((void**)&bufH, g_bufH);

    cudaFuncSetAttribute(k_gemm_mma, cudaFuncAttributeMaxDynamicSharedMemorySize,
                         (int)GEMM_SMEM);

    int nb256_N = (N + 255) / 256;
    int nb256_E = (E + 255) / 256;
    int nbScan  = (N + SCAN_BS - 1) / SCAN_BS;
    int nbGemm  = (N + 127) / 128;
    int nbHead  = (N + 63) / 64;
    int nbAgg   = (N + 7) / 8;

    // graph structure prep
    k_init_deg<<<nb256_N, 256>>>(N);
    k_count_deg<<<nb256_E, 256>>>(dst, E);
    k_dinv<<<nb256_N, 256>>>(N);
    k_scan1<<<nbScan, SCAN_BS>>>(N);
    k_scan2<<<1, 32>>>(nbScan);
    k_scan3<<<nbScan, SCAN_BS>>>(N);
    k_scatter<<<nb256_E, 256>>>(src, dst, E);

    // layer 1
    k_gemm_mma<<<nbGemm, 256, GEMM_SMEM>>>(x, W1, nullptr, nullptr, bufH, N, 0, 0, 1);
    k_aggregate<<<nbAgg, 256>>>(bufH, b1, bufA, N);
    // layer 2
    k_gemm_mma<<<nbGemm, 256, GEMM_SMEM>>>(bufA, W2, nullptr, nullptr, bufH, N, 0, 0, 1);
    k_aggregate<<<nbAgg, 256>>>(bufH, b2, bufB, N);
    // layer 3
    k_gemm_mma<<<nbGemm, 256, GEMM_SMEM>>>(bufB, W3, nullptr, nullptr, bufH, N, 0, 0, 1);
    k_aggregate<<<nbAgg, 256>>>(bufH, b3, bufA, N);
    // FFN
    k_gemm_mma<<<nbGemm, 256, GEMM_SMEM>>>(bufA, fW1, fb1, bufT, nullptr, N, 1, 1, 0);
    k_head<<<nbHead, 256>>>(bufT, fW2, fb2, out, N);
}

// round 6
// speedup vs baseline: 2.2021x; 1.1693x over previous
#include <cuda_runtime.h>
#include <cuda_fp16.h>
#include <cstdint>
#include <cstddef>

#define N_NODES   100000
#define N_EDGES   1600000
#define DIM       128
#define N_CLASSES 10

#define SCAN_BS   1024
#define SCAN_NB   ((N_NODES + SCAN_BS - 1) / SCAN_BS)

// ---------------- scratch (static __device__, no allocation) ----------------
__device__ __half g_bufX[(size_t)N_NODES * DIM];   // x in fp16
__device__ __half g_bufH[(size_t)N_NODES * DIM];   // GEMM out h (gather target)
__device__ __half g_bufP[(size_t)N_NODES * DIM];   // aggregate out (GEMM A input)
__device__ float  g_bufT[(size_t)N_NODES * DIM];   // FFN hidden (fp32, head input)
__device__ float  g_dinv[N_NODES];
__device__ int    g_cnt[N_NODES];
__device__ int    g_off[N_NODES + 1];
__device__ int    g_cur[N_NODES];
__device__ int2   g_edge[N_EDGES];                 // (src, norm bits)
__device__ int    g_bsum[SCAN_NB];
__device__ int    g_bpref[SCAN_NB];

// ---------------- prep kernels ----------------
__global__ void k_init_deg(int n) {
    int i = blockIdx.x * blockDim.x + threadIdx.x;
    if (i < n) g_cnt[i] = 1;
}
__global__ void k_count_deg(const int* __restrict__ dst, int e) {
    int i = blockIdx.x * blockDim.x + threadIdx.x;
    if (i < e) atomicAdd(&g_cnt[dst[i]], 1);
}
__global__ void k_dinv(int n) {
    int i = blockIdx.x * blockDim.x + threadIdx.x;
    if (i < n) g_dinv[i] = rsqrtf((float)g_cnt[i]);
}
__global__ void k_scan1(int n) {
    __shared__ int sh[SCAN_BS];
    int i = blockIdx.x * SCAN_BS + threadIdx.x;
    int v = (i < n) ? (g_cnt[i] - 1) : 0;
    sh[threadIdx.x] = v;
    __syncthreads();
    for (int ofs = 1; ofs < SCAN_BS; ofs <<= 1) {
        int t = (threadIdx.x >= ofs) ? sh[threadIdx.x - ofs] : 0;
        __syncthreads();
        sh[threadIdx.x] += t;
        __syncthreads();
    }
    if (i < n) g_cur[i] = sh[threadIdx.x];
    if (threadIdx.x == SCAN_BS - 1) g_bsum[blockIdx.x] = sh[SCAN_BS - 1];
}
__global__ void k_scan2(int nb) {
    if (threadIdx.x == 0 && blockIdx.x == 0) {
        int s = 0;
        for (int b = 0; b < nb; ++b) { s += g_bsum[b]; g_bpref[b] = s; }
    }
}
__global__ void k_scan3(int n) {
    int i = blockIdx.x * SCAN_BS + threadIdx.x;
    if (i >= n) return;
    int b = blockIdx.x;
    int inc = g_cur[i] + (b > 0 ? g_bpref[b - 1] : 0);
    int c = g_cnt[i] - 1;
    int ex = inc - c;
    g_off[i] = ex;
    g_cur[i] = ex;
    if (i == n - 1) g_off[n] = inc;
}
__global__ void k_scatter(const int* __restrict__ src, const int* __restrict__ dst, int e) {
    int i = blockIdx.x * blockDim.x + threadIdx.x;
    if (i >= e) return;
    int s = src[i], d = dst[i];
    int p = atomicAdd(&g_cur[d], 1);
    float nm = g_dinv[s] * g_dinv[d];
    g_edge[p] = make_int2(s, __float_as_int(nm));
}

// x (fp32) -> fp16
__global__ void k_x2h(const float* __restrict__ x, __half* __restrict__ o, int n128) {
    int i = blockIdx.x * blockDim.x + threadIdx.x;   // per 4 floats
    if (i >= n128) return;
    float4 v = __ldg((const float4*)(x + (size_t)i * 4));
    __half2 lo = __float22half2_rn(make_float2(v.x, v.y));
    __half2 hi = __float22half2_rn(make_float2(v.z, v.w));
    *(uint2*)(o + (size_t)i * 4) = make_uint2(*(uint32_t*)&lo, *(uint32_t*)&hi);
}

// ---------------- fp16 mma.sync GEMM: C[M,128] = A[M,128] @ W[128,128] ----------------
// 128x128 tile per CTA, 256 threads = 8 warps (4 M x 2 N), warp tile 32x64.
// mma.m16n8k16.f32.f16.f16.f32: 8 K-steps.
#define PADH 136   // halves per smem row: ((136/2)*g + t) mod 32 covers all banks
#define GEMM_SMEM_H (2 * 128 * PADH * sizeof(__half))

__device__ __forceinline__ void mma_f16(float c[4], const uint32_t a[4],
                                        uint32_t b0, uint32_t b1) {
    asm volatile(
        "mma.sync.aligned.m16n8k16.row.col.f32.f16.f16.f32 "
        "{%0,%1,%2,%3}, {%4,%5,%6,%7}, {%8,%9}, {%0,%1,%2,%3};"
        : "+f"(c[0]), "+f"(c[1]), "+f"(c[2]), "+f"(c[3])
        : "r"(a[0]), "r"(a[1]), "r"(a[2]), "r"(a[3]), "r"(b0), "r"(b1));
}

// out_half: 1 -> fp16 C16 ; 0 -> fp32 C32
__global__ __launch_bounds__(256) void k_gemm_mma(
    const __half* __restrict__ A, const float* __restrict__ W,
    const float* __restrict__ bias, float* __restrict__ C32,
    __half* __restrict__ C16,
    int M, int has_bias, int do_relu, int out_half)
{
    extern __shared__ __half smh[];
    __half* sA = smh;                  // [128][PADH]
    __half* sW = smh + 128 * PADH;     // transposed: [n][k]

    int tid = threadIdx.x;
    int wid = tid >> 5, lane = tid & 31;
    int gID = lane >> 2, tig = lane & 3;
    int row0 = blockIdx.x * 128;

    // stage A: 128 rows x 128 halves, uint4 = 8 halves
#pragma unroll
    for (int i = 0; i < 8; ++i) {
        int fid = i * 256 + tid;            // 2048 chunks
        int r = fid >> 4, c8 = (fid & 15) << 3;
        uint4 v = make_uint4(0, 0, 0, 0);
        int gr = row0 + r;
        if (gr < M) v = __ldg((const uint4*)(A + (size_t)gr * 128 + c8));
        *(uint4*)(sA + r * PADH + c8) = v;
    }
    // stage W transposed: sW[n][k] = fp16(W[k][n])
#pragma unroll
    for (int i = 0; i < 64; ++i) {
        int o = i * 256 + tid;              // 16384
        int n = o & 127, k = o >> 7;
        sW[n * PADH + k] = __float2half_rn(__ldg(W + (size_t)k * 128 + n));
    }
    __syncthreads();

    int wm = (wid & 3) * 32;
    int wn = (wid >> 2) * 64;

    float acc[2][8][4];
#pragma unroll
    for (int mf = 0; mf < 2; ++mf)
#pragma unroll
        for (int nf = 0; nf < 8; ++nf)
#pragma unroll
            for (int j = 0; j < 4; ++j) acc[mf][nf][j] = 0.f;

#pragma unroll
    for (int k0 = 0; k0 < 128; k0 += 16) {
        uint32_t a[2][4];
#pragma unroll
        for (int mf = 0; mf < 2; ++mf) {
            int mr = wm + mf * 16;
            a[mf][0] = *(const uint32_t*)(sA + (mr + gID)     * PADH + k0 + 2 * tig);
            a[mf][1] = *(const uint32_t*)(sA + (mr + gID + 8) * PADH + k0 + 2 * tig);
            a[mf][2] = *(const uint32_t*)(sA + (mr + gID)     * PADH + k0 + 2 * tig + 8);
            a[mf][3] = *(const uint32_t*)(sA + (mr + gID + 8) * PADH + k0 + 2 * tig + 8);
        }
#pragma unroll
        for (int nf = 0; nf < 8; ++nf) {
            int nc = wn + nf * 8;
            uint32_t b0 = *(const uint32_t*)(sW + (nc + gID) * PADH + k0 + 2 * tig);
            uint32_t b1 = *(const uint32_t*)(sW + (nc + gID) * PADH + k0 + 2 * tig + 8);
            mma_f16(acc[0][nf], a[0], b0, b1);
            mma_f16(acc[1][nf], a[1], b0, b1);
        }
    }

#pragma unroll
    for (int mf = 0; mf < 2; ++mf) {
        int r_lo = row0 + wm + mf * 16 + gID;
        int r_hi = r_lo + 8;
#pragma unroll
        for (int nf = 0; nf < 8; ++nf) {
            int col = wn + nf * 8 + tig * 2;
            float2 vlo = make_float2(acc[mf][nf][0], acc[mf][nf][1]);
            float2 vhi = make_float2(acc[mf][nf][2], acc[mf][nf][3]);
            if (has_bias) {
                float bx = bias[col], by = bias[col + 1];
                vlo.x += bx; vlo.y += by;
                vhi.x += bx; vhi.y += by;
            }
            if (do_relu) {
                vlo.x = fmaxf(vlo.x, 0.f); vlo.y = fmaxf(vlo.y, 0.f);
                vhi.x = fmaxf(vhi.x, 0.f); vhi.y = fmaxf(vhi.y, 0.f);
            }
            if (out_half) {
                if (r_lo < M) *(__half2*)(C16 + (size_t)r_lo * 128 + col) = __float22half2_rn(vlo);
                if (r_hi < M) *(__half2*)(C16 + (size_t)r_hi * 128 + col) = __float22half2_rn(vhi);
            } else {
                if (r_lo < M) *(float2*)(C32 + (size_t)r_lo * 128 + col) = vlo;
                if (r_hi < M) *(float2*)(C32 + (size_t)r_hi * 128 + col) = vhi;
            }
        }
    }
}

// ---------------- CSR aggregation: one warp per node, 8-deep MLP, fp16 in/out ----------------
__global__ __launch_bounds__(256) void k_aggregate(
    const __half* __restrict__ h, const float* __restrict__ bias,
    __half* __restrict__ out, int N)
{
    int warp = (blockIdx.x << 3) + (threadIdx.x >> 5);
    if (warp >= N) return;
    int i = warp;
    int lane = threadIdx.x & 31;

    const __half* hcol = h + lane * 4;
    float4 acc = make_float4(0.f, 0.f, 0.f, 0.f);

    int e0 = g_off[i], e1 = g_off[i + 1];
    for (int e = e0; e < e1; e += 8) {
        int n = e1 - e;
        int2 rec[8];
        uint2 hv[8];
#pragma unroll
        for (int j = 0; j < 8; ++j)
            if (j < n) rec[j] = __ldg(&g_edge[e + j]);
#pragma unroll
        for (int j = 0; j < 8; ++j)
            if (j < n) hv[j] = __ldg((const uint2*)(hcol + (size_t)rec[j].x * 128));
#pragma unroll
        for (int j = 0; j < 8; ++j) {
            if (j < n) {
                float nm = __int_as_float(rec[j].y);
                float2 a = __half22float2(*(const __half2*)&hv[j].x);
                float2 b = __half22float2(*(const __half2*)&hv[j].y);
                acc.x = fmaf(nm, a.x, acc.x); acc.y = fmaf(nm, a.y, acc.y);
                acc.z = fmaf(nm, b.x, acc.z); acc.w = fmaf(nm, b.y, acc.w);
            }
        }
    }

    float di = g_dinv[i];
    float dii = di * di;
    uint2 us = __ldg((const uint2*)(hcol + (size_t)i * 128));
    float2 sa = __half22float2(*(const __half2*)&us.x);
    float2 sb = __half22float2(*(const __half2*)&us.y);
    float4 bv = __ldg((const float4*)(bias + lane * 4));
    acc.x = fmaxf(fmaf(dii, sa.x, acc.x) + bv.x, 0.f);
    acc.y = fmaxf(fmaf(dii, sa.y, acc.y) + bv.y, 0.f);
    acc.z = fmaxf(fmaf(dii, sb.x, acc.z) + bv.z, 0.f);
    acc.w = fmaxf(fmaf(dii, sb.y, acc.w) + bv.w, 0.f);

    __half2 lo = __float22half2_rn(make_float2(acc.x, acc.y));
    __half2 hi = __float22half2_rn(make_float2(acc.z, acc.w));
    *(uint2*)(out + (size_t)i * 128 + lane * 4) =
        make_uint2(*(uint32_t*)&lo, *(uint32_t*)&hi);
}

// ---------------- head: out[M,10] = H[M,128] @ W[128,10] + b ----------------
__global__ __launch_bounds__(256) void k_head(
    const float* __restrict__ H, const float* __restrict__ W,
    const float* __restrict__ b, float* __restrict__ out, int M)
{
    __shared__ float sH[64][129];
    __shared__ float sW[128 * N_CLASSES];
    __shared__ float sb_[N_CLASSES];

    int tid = threadIdx.x;
    int row0 = blockIdx.x * 64;

    for (int i = tid; i < 128 * N_CLASSES; i += 256) sW[i] = W[i];
    if (tid < N_CLASSES) sb_[tid] = b[tid];

#pragma unroll
    for (int t = 0; t < 8; ++t) {
        int idx4 = tid + t * 256;
        int r = idx4 >> 5;
        int c = (idx4 & 31) << 2;
        int gr = row0 + r;
        float4 v = make_float4(0.f, 0.f, 0.f, 0.f);
        if (gr < M) v = *(const float4*)(H + (size_t)gr * 128 + c);
        sH[r][c + 0] = v.x; sH[r][c + 1] = v.y;
        sH[r][c + 2] = v.z; sH[r][c + 3] = v.w;
    }
    __syncthreads();

    for (int o = tid; o < 64 * N_CLASSES; o += 256) {
        int r = o / N_CLASSES, c = o % N_CLASSES;
        int gr = row0 + r;
        if (gr >= M) continue;
        float acc = sb_[c];
#pragma unroll
        for (int k = 0; k < 128; ++k)
            acc = fmaf(sH[r][k], sW[k * N_CLASSES + c], acc);
        out[(size_t)gr * N_CLASSES + c] = acc;
    }
}

// ---------------- host launch ----------------
extern "C" void kernel_launch(void* const* d_in, const int* in_sizes, int n_in,
                              void* d_out, int out_size)
{
    const float* x   = (const float*)d_in[0];
    const int*   ei  = (const int*)d_in[1];
    const float* W1  = (const float*)d_in[2];
    const float* b1  = (const float*)d_in[3];
    const float* W2  = (const float*)d_in[4];
    const float* b2  = (const float*)d_in[5];
    const float* W3  = (const float*)d_in[6];
    const float* b3  = (const float*)d_in[7];
    const float* fW1 = (const float*)d_in[8];
    const float* fb1 = (const float*)d_in[9];
    const float* fW2 = (const float*)d_in[10];
    const float* fb2 = (const float*)d_in[11];
    float* out = (float*)d_out;

    int N = in_sizes[0] / DIM;
    int E = in_sizes[1] / 2;
    const int* src = ei;
    const int* dst = ei + E;

    __half *bufX, *bufH, *bufP;
    float* bufT;
    cudaGetSymbolAddress((void**)&bufX, g_bufX);
    cudaGetSymbolAddress((void**)&bufH, g_bufH);
    cudaGetSymbolAddress((void**)&bufP, g_bufP);
    cudaGetSymbolAddress((void**)&bufT, g_bufT);

    cudaFuncSetAttribute(k_gemm_mma, cudaFuncAttributeMaxDynamicSharedMemorySize,
                         (int)GEMM_SMEM_H);

    int nb256_N = (N + 255) / 256;
    int nb256_E = (E + 255) / 256;
    int nbScan  = (N + SCAN_BS - 1) / SCAN_BS;
    int nbGemm  = (N + 127) / 128;
    int nbHead  = (N + 63) / 64;
    int nbAgg   = (N + 7) / 8;
    int nbCvt   = (N * DIM / 4 + 255) / 256;

    // graph structure prep
    k_init_deg<<<nb256_N, 256>>>(N);
    k_count_deg<<<nb256_E, 256>>>(dst, E);
    k_dinv<<<nb256_N, 256>>>(N);
    k_scan1<<<nbScan, SCAN_BS>>>(N);
    k_scan2<<<1, 32>>>(nbScan);
    k_scan3<<<nbScan, SCAN_BS>>>(N);
    k_scatter<<<nb256_E, 256>>>(src, dst, E);
    k_x2h<<<nbCvt, 256>>>(x, bufX, N * DIM / 4);

    // layer 1
    k_gemm_mma<<<nbGemm, 256, GEMM_SMEM_H>>>(bufX, W1, nullptr, nullptr, bufH, N, 0, 0, 1);
    k_aggregate<<<nbAgg, 256>>>(bufH, b1, bufP, N);
    // layer 2
    k_gemm_mma<<<nbGemm, 256, GEMM_SMEM_H>>>(bufP, W2, nullptr, nullptr, bufH, N, 0, 0, 1);
    k_aggregate<<<nbAgg, 256>>>(bufH, b2, bufP, N);
    // layer 3
    k_gemm_mma<<<nbGemm, 256, GEMM_SMEM_H>>>(bufP, W3, nullptr, nullptr, bufH, N, 0, 0, 1);
    k_aggregate<<<nbAgg, 256>>>(bufH, b3, bufP, N);
    // FFN
    k_gemm_mma<<<nbGemm, 256, GEMM_SMEM_H>>>(bufP, fW1, fb1, bufT, nullptr, N, 1, 1, 0);
    k_head<<<nbHead, 256>>>(bufT, fW2, fb2, out, N);
}

// round 7
// speedup vs baseline: 2.3034x; 1.0460x over previous
#include <cuda_runtime.h>
#include <cuda_fp16.h>
#include <cstdint>
#include <cstddef>

#define N_NODES   100000
#define N_EDGES   1600000
#define DIM       128
#define N_CLASSES 10

#define SCAN_BS   1024
#define SCAN_NB   ((N_NODES + SCAN_BS - 1) / SCAN_BS)

// ---------------- scratch (static __device__, no allocation) ----------------
__device__ __half g_bufH[(size_t)N_NODES * DIM];   // GEMM out h (gather target)
__device__ __half g_bufP[(size_t)N_NODES * DIM];   // aggregate out (GEMM A input)
__device__ __half g_bufF[(size_t)N_NODES * DIM];   // FFN hidden (fp16, head input)
__device__ __half g_Wt[4][DIM * DIM];              // transposed fp16 weights [n][k]
__device__ float  g_dinv[N_NODES];
__device__ int    g_cnt[N_NODES];                  // real-edge in-degree
__device__ int    g_off[N_NODES + 1];
__device__ int    g_cur[N_NODES];
__device__ int2   g_edge[N_EDGES];                 // (src, norm bits)
__device__ int    g_bsum[SCAN_NB];
__device__ int    g_bpref[SCAN_NB];

// ---------------- prep kernels ----------------
__global__ void k_count_deg(const int* __restrict__ dst, int e) {
    int i = blockIdx.x * blockDim.x + threadIdx.x;
    if (i < e) atomicAdd(&g_cnt[dst[i]], 1);
}
__global__ void k_dinv(int n) {
    int i = blockIdx.x * blockDim.x + threadIdx.x;
    if (i < n) g_dinv[i] = rsqrtf((float)(g_cnt[i] + 1));  // +1 self-loop
}
__global__ void k_scan1(int n) {
    __shared__ int sh[SCAN_BS];
    int i = blockIdx.x * SCAN_BS + threadIdx.x;
    int v = (i < n) ? g_cnt[i] : 0;
    sh[threadIdx.x] = v;
    __syncthreads();
    for (int ofs = 1; ofs < SCAN_BS; ofs <<= 1) {
        int t = (threadIdx.x >= ofs) ? sh[threadIdx.x - ofs] : 0;
        __syncthreads();
        sh[threadIdx.x] += t;
        __syncthreads();
    }
    if (i < n) g_cur[i] = sh[threadIdx.x];
    if (threadIdx.x == SCAN_BS - 1) g_bsum[blockIdx.x] = sh[SCAN_BS - 1];
}
__global__ void k_scan2(int nb) {
    if (threadIdx.x == 0 && blockIdx.x == 0) {
        int s = 0;
        for (int b = 0; b < nb; ++b) { g_bpref[b] = s; s += g_bsum[b]; }
    }
}
__global__ void k_scan3(int n) {
    int i = blockIdx.x * SCAN_BS + threadIdx.x;
    if (i >= n) return;
    int inc = g_cur[i] + g_bpref[blockIdx.x];
    int ex = inc - g_cnt[i];
    g_off[i] = ex;
    g_cur[i] = ex;
    if (i == n - 1) g_off[n] = inc;
}
__global__ void k_scatter(const int* __restrict__ src, const int* __restrict__ dst, int e) {
    int i = blockIdx.x * blockDim.x + threadIdx.x;
    if (i >= e) return;
    int s = src[i], d = dst[i];
    int p = atomicAdd(&g_cur[d], 1);
    float nm = g_dinv[s] * g_dinv[d];
    g_edge[p] = make_int2(s, __float_as_int(nm));
}

// smem-tiled transpose+convert: Wt[n][k] = fp16(W[k][n]); W is 128x128
__global__ void k_transW(const float* __restrict__ W, __half* __restrict__ Wt) {
    __shared__ float tile[32][33];
    int bn = blockIdx.x * 32, bk = blockIdx.y * 32;
    int tx = threadIdx.x, ty = threadIdx.y;          // 32 x 8
#pragma unroll
    for (int r = 0; r < 32; r += 8)
        tile[ty + r][tx] = W[(size_t)(bk + ty + r) * 128 + bn + tx];
    __syncthreads();
#pragma unroll
    for (int r = 0; r < 32; r += 8)
        Wt[(size_t)(bn + ty + r) * 128 + bk + tx] = __float2half_rn(tile[tx][ty + r]);
}

// ---------------- fp16 mma.sync GEMM: C[M,128] = A[M,128] @ W[128,128] ----------------
#define PADH 136
#define GEMM_SMEM_H (2 * 128 * PADH * sizeof(__half))

__device__ __forceinline__ void mma_f16(float c[4], const uint32_t a[4],
                                        uint32_t b0, uint32_t b1) {
    asm volatile(
        "mma.sync.aligned.m16n8k16.row.col.f32.f16.f16.f32 "
        "{%0,%1,%2,%3}, {%4,%5,%6,%7}, {%8,%9}, {%0,%1,%2,%3};"
        : "+f"(c[0]), "+f"(c[1]), "+f"(c[2]), "+f"(c[3])
        : "r"(a[0]), "r"(a[1]), "r"(a[2]), "r"(a[3]), "r"(b0), "r"(b1));
}

// A input: fp16 (A16) or fp32 (A32, converted in staging). Output: fp16 C16.
__global__ __launch_bounds__(256) void k_gemm_mma(
    const __half* __restrict__ A16, const float* __restrict__ A32,
    const __half* __restrict__ Wt, const float* __restrict__ bias,
    __half* __restrict__ C16,
    int M, int has_bias, int do_relu)
{
    extern __shared__ __half smh[];
    __half* sA = smh;                  // [128][PADH]
    __half* sW = smh + 128 * PADH;     // [n][k]

    int tid = threadIdx.x;
    int wid = tid >> 5, lane = tid & 31;
    int gID = lane >> 2, tig = lane & 3;
    int row0 = blockIdx.x * 128;

    if (A32) {
        // stage A from fp32, converting: 4096 chunks of 4 floats
#pragma unroll
        for (int i = 0; i < 16; ++i) {
            int fid = i * 256 + tid;
            int r = fid >> 5, c4 = (fid & 31) << 2;
            float4 v = make_float4(0.f, 0.f, 0.f, 0.f);
            int gr = row0 + r;
            if (gr < M) v = __ldg((const float4*)(A32 + (size_t)gr * 128 + c4));
            __half2 lo = __float22half2_rn(make_float2(v.x, v.y));
            __half2 hi = __float22half2_rn(make_float2(v.z, v.w));
            *(uint2*)(sA + r * PADH + c4) = make_uint2(*(uint32_t*)&lo, *(uint32_t*)&hi);
        }
    } else {
        // stage A fp16: 2048 chunks of 8 halves
#pragma unroll
        for (int i = 0; i < 8; ++i) {
            int fid = i * 256 + tid;
            int r = fid >> 4, c8 = (fid & 15) << 3;
            uint4 v = make_uint4(0, 0, 0, 0);
            int gr = row0 + r;
            if (gr < M) v = __ldg((const uint4*)(A16 + (size_t)gr * 128 + c8));
            *(uint4*)(sA + r * PADH + c8) = v;
        }
    }
    // stage Wt (pre-transposed fp16): coalesced uint4 copy
#pragma unroll
    for (int i = 0; i < 8; ++i) {
        int fid = i * 256 + tid;
        int n = fid >> 4, k8 = (fid & 15) << 3;
        uint4 v = __ldg((const uint4*)(Wt + (size_t)n * 128 + k8));
        *(uint4*)(sW + n * PADH + k8) = v;
    }
    __syncthreads();

    int wm = (wid & 3) * 32;
    int wn = (wid >> 2) * 64;

    float acc[2][8][4];
#pragma unroll
    for (int mf = 0; mf < 2; ++mf)
#pragma unroll
        for (int nf = 0; nf < 8; ++nf)
#pragma unroll
            for (int j = 0; j < 4; ++j) acc[mf][nf][j] = 0.f;

#pragma unroll
    for (int k0 = 0; k0 < 128; k0 += 16) {
        uint32_t a[2][4];
#pragma unroll
        for (int mf = 0; mf < 2; ++mf) {
            int mr = wm + mf * 16;
            a[mf][0] = *(const uint32_t*)(sA + (mr + gID)     * PADH + k0 + 2 * tig);
            a[mf][1] = *(const uint32_t*)(sA + (mr + gID + 8) * PADH + k0 + 2 * tig);
            a[mf][2] = *(const uint32_t*)(sA + (mr + gID)     * PADH + k0 + 2 * tig + 8);
            a[mf][3] = *(const uint32_t*)(sA + (mr + gID + 8) * PADH + k0 + 2 * tig + 8);
        }
#pragma unroll
        for (int nf = 0; nf < 8; ++nf) {
            int nc = wn + nf * 8;
            uint32_t b0 = *(const uint32_t*)(sW + (nc + gID) * PADH + k0 + 2 * tig);
            uint32_t b1 = *(const uint32_t*)(sW + (nc + gID) * PADH + k0 + 2 * tig + 8);
            mma_f16(acc[0][nf], a[0], b0, b1);
            mma_f16(acc[1][nf], a[1], b0, b1);
        }
    }

#pragma unroll
    for (int mf = 0; mf < 2; ++mf) {
        int r_lo = row0 + wm + mf * 16 + gID;
        int r_hi = r_lo + 8;
#pragma unroll
        for (int nf = 0; nf < 8; ++nf) {
            int col = wn + nf * 8 + tig * 2;
            float2 vlo = make_float2(acc[mf][nf][0], acc[mf][nf][1]);
            float2 vhi = make_float2(acc[mf][nf][2], acc[mf][nf][3]);
            if (has_bias) {
                float bx = bias[col], by = bias[col + 1];
                vlo.x += bx; vlo.y += by;
                vhi.x += bx; vhi.y += by;
            }
            if (do_relu) {
                vlo.x = fmaxf(vlo.x, 0.f); vlo.y = fmaxf(vlo.y, 0.f);
                vhi.x = fmaxf(vhi.x, 0.f); vhi.y = fmaxf(vhi.y, 0.f);
            }
            if (r_lo < M) *(__half2*)(C16 + (size_t)r_lo * 128 + col) = __float22half2_rn(vlo);
            if (r_hi < M) *(__half2*)(C16 + (size_t)r_hi * 128 + col) = __float22half2_rn(vhi);
        }
    }
}

// ---------------- CSR aggregation: one warp per node, 8-deep MLP, fp16 in/out ----------------
__global__ __launch_bounds__(256) void k_aggregate(
    const __half* __restrict__ h, const float* __restrict__ bias,
    __half* __restrict__ out, int N)
{
    int warp = (blockIdx.x << 3) + (threadIdx.x >> 5);
    if (warp >= N) return;
    int i = warp;
    int lane = threadIdx.x & 31;

    const __half* hcol = h + lane * 4;
    float4 acc = make_float4(0.f, 0.f, 0.f, 0.f);

    int e0 = g_off[i], e1 = g_off[i + 1];
    for (int e = e0; e < e1; e += 8) {
        int n = e1 - e;
        int2 rec[8];
        uint2 hv[8];
#pragma unroll
        for (int j = 0; j < 8; ++j)
            if (j < n) rec[j] = __ldg(&g_edge[e + j]);
#pragma unroll
        for (int j = 0; j < 8; ++j)
            if (j < n) hv[j] = __ldg((const uint2*)(hcol + (size_t)rec[j].x * 128));
#pragma unroll
        for (int j = 0; j < 8; ++j) {
            if (j < n) {
                float nm = __int_as_float(rec[j].y);
                float2 a = __half22float2(*(const __half2*)&hv[j].x);
                float2 b = __half22float2(*(const __half2*)&hv[j].y);
                acc.x = fmaf(nm, a.x, acc.x); acc.y = fmaf(nm, a.y, acc.y);
                acc.z = fmaf(nm, b.x, acc.z); acc.w = fmaf(nm, b.y, acc.w);
            }
        }
    }

    float di = g_dinv[i];
    float dii = di * di;
    uint2 us = __ldg((const uint2*)(hcol + (size_t)i * 128));
    float2 sa = __half22float2(*(const __half2*)&us.x);
    float2 sb = __half22float2(*(const __half2*)&us.y);
    float4 bv = __ldg((const float4*)(bias + lane * 4));
    acc.x = fmaxf(fmaf(dii, sa.x, acc.x) + bv.x, 0.f);
    acc.y = fmaxf(fmaf(dii, sa.y, acc.y) + bv.y, 0.f);
    acc.z = fmaxf(fmaf(dii, sb.x, acc.z) + bv.z, 0.f);
    acc.w = fmaxf(fmaf(dii, sb.y, acc.w) + bv.w, 0.f);

    __half2 lo = __float22half2_rn(make_float2(acc.x, acc.y));
    __half2 hi = __float22half2_rn(make_float2(acc.z, acc.w));
    *(uint2*)(out + (size_t)i * 128 + lane * 4) =
        make_uint2(*(uint32_t*)&lo, *(uint32_t*)&hi);
}

// ---------------- head: out[M,10] = H[M,128] @ W[128,10] + b, H fp16 ----------------
__global__ __launch_bounds__(256) void k_head(
    const __half* __restrict__ H, const float* __restrict__ W,
    const float* __restrict__ b, float* __restrict__ out, int M)
{
    __shared__ float sH[64][129];
    __shared__ float sW[128 * N_CLASSES];
    __shared__ float sb_[N_CLASSES];

    int tid = threadIdx.x;
    int row0 = blockIdx.x * 64;

    for (int i = tid; i < 128 * N_CLASSES; i += 256) sW[i] = W[i];
    if (tid < N_CLASSES) sb_[tid] = b[tid];

    // 64 rows x 128 halves = 1024 uint4 chunks
#pragma unroll
    for (int t = 0; t < 4; ++t) {
        int idx = tid + t * 256;
        int r = idx >> 4, c8 = (idx & 15) << 3;
        int gr = row0 + r;
        uint4 v = make_uint4(0, 0, 0, 0);
        if (gr < M) v = __ldg((const uint4*)(H + (size_t)gr * 128 + c8));
        const __half2* p = (const __half2*)&v;
#pragma unroll
        for (int j = 0; j < 4; ++j) {
            float2 f = __half22float2(p[j]);
            sH[r][c8 + 2 * j]     = f.x;
            sH[r][c8 + 2 * j + 1] = f.y;
        }
    }
    __syncthreads();

    for (int o = tid; o < 64 * N_CLASSES; o += 256) {
        int r = o / N_CLASSES, c = o % N_CLASSES;
        int gr = row0 + r;
        if (gr >= M) continue;
        float acc = sb_[c];
#pragma unroll
        for (int k = 0; k < 128; ++k)
            acc = fmaf(sH[r][k], sW[k * N_CLASSES + c], acc);
        out[(size_t)gr * N_CLASSES + c] = acc;
    }
}

// ---------------- host launch ----------------
extern "C" void kernel_launch(void* const* d_in, const int* in_sizes, int n_in,
                              void* d_out, int out_size)
{
    const float* x   = (const float*)d_in[0];
    const int*   ei  = (const int*)d_in[1];
    const float* W1  = (const float*)d_in[2];
    const float* b1  = (const float*)d_in[3];
    const float* W2  = (const float*)d_in[4];
    const float* b2  = (const float*)d_in[5];
    const float* W3  = (const float*)d_in[6];
    const float* b3  = (const float*)d_in[7];
    const float* fW1 = (const float*)d_in[8];
    const float* fb1 = (const float*)d_in[9];
    const float* fW2 = (const float*)d_in[10];
    const float* fb2 = (const float*)d_in[11];
    float* out = (float*)d_out;

    int N = in_sizes[0] / DIM;
    int E = in_sizes[1] / 2;
    const int* src = ei;
    const int* dst = ei + E;

    __half *bufH, *bufP, *bufF, *wt;
    int* cntp;
    cudaGetSymbolAddress((void**)&bufH, g_bufH);
    cudaGetSymbolAddress((void**)&bufP, g_bufP);
    cudaGetSymbolAddress((void**)&bufF, g_bufF);
    cudaGetSymbolAddress((void**)&wt,   g_Wt);
    cudaGetSymbolAddress((void**)&cntp, g_cnt);
    __half* Wt1 = wt;
    __half* Wt2 = wt + DIM * DIM;
    __half* Wt3 = wt + 2 * DIM * DIM;
    __half* Wt4 = wt + 3 * DIM * DIM;

    cudaFuncSetAttribute(k_gemm_mma, cudaFuncAttributeMaxDynamicSharedMemorySize,
                         (int)GEMM_SMEM_H);

    int nb256_N = (N + 255) / 256;
    int nb256_E = (E + 255) / 256;
    int nbScan  = (N + SCAN_BS - 1) / SCAN_BS;
    int nbGemm  = (N + 127) / 128;
    int nbHead  = (N + 63) / 64;
    int nbAgg   = (N + 7) / 8;

    // graph structure prep
    cudaMemsetAsync(cntp, 0, (size_t)N * sizeof(int));
    k_count_deg<<<nb256_E, 256>>>(dst, E);
    k_dinv<<<nb256_N, 256>>>(N);
    k_scan1<<<nbScan, SCAN_BS>>>(N);
    k_scan2<<<1, 32>>>(nbScan);
    k_scan3<<<nbScan, SCAN_BS>>>(N);
    k_scatter<<<nb256_E, 256>>>(src, dst, E);

    // weight pre-transpose (fp16)
    dim3 trGrid(4, 4), trBlk(32, 8);
    k_transW<<<trGrid, trBlk>>>(W1, Wt1);
    k_transW<<<trGrid, trBlk>>>(W2, Wt2);
    k_transW<<<trGrid, trBlk>>>(W3, Wt3);
    k_transW<<<trGrid, trBlk>>>(fW1, Wt4);

    // layer 1 (A from fp32 x, converted in staging)
    k_gemm_mma<<<nbGemm, 256, GEMM_SMEM_H>>>(nullptr, x, Wt1, nullptr, bufH, N, 0, 0);
    k_aggregate<<<nbAgg, 256>>>(bufH, b1, bufP, N);
    // layer 2
    k_gemm_mma<<<nbGemm, 256, GEMM_SMEM_H>>>(bufP, nullptr, Wt2, nullptr, bufH, N, 0, 0);
    k_aggregate<<<nbAgg, 256>>>(bufH, b2, bufP, N);
    // layer 3
    k_gemm_mma<<<nbGemm, 256, GEMM_SMEM_H>>>(bufP, nullptr, Wt3, nullptr, bufH, N, 0, 0);
    k_aggregate<<<nbAgg, 256>>>(bufH, b3, bufP, N);
    // FFN (fp16 out)
    k_gemm_mma<<<nbGemm, 256, GEMM_SMEM_H>>>(bufP, nullptr, Wt4, fb1, bufF, N, 1, 1);
    k_head<<<nbHead, 256>>>(bufF, fW2, fb2, out, N);
}

// round 8
// speedup vs baseline: 2.4463x; 1.0620x over previous
#include <cuda_runtime.h>
#include <cuda_fp16.h>
#include <cstdint>
#include <cstddef>

#define N_NODES   100000
#define N_EDGES   1600000
#define DIM       128
#define N_CLASSES 10

#define SCAN_BS   1024
#define SCAN_NB   ((N_NODES + SCAN_BS - 1) / SCAN_BS)   // 98 (<=128)

// ---------------- scratch (static __device__, no allocation) ----------------
__device__ __half g_bufH[(size_t)N_NODES * DIM];   // GEMM out h (gather target)
__device__ __half g_bufP[(size_t)N_NODES * DIM];   // aggregate out (GEMM A input)
__device__ __half g_Wt[4][DIM * DIM];              // transposed fp16 weights [n][k]
__device__ float  g_dinv[N_NODES];
__device__ int    g_cnt[N_NODES];                  // real-edge in-degree
__device__ int    g_off[N_NODES + 1];
__device__ int    g_cur[N_NODES];
__device__ int2   g_edge[N_EDGES];                 // (src, norm bits)
__device__ int    g_bsum[SCAN_NB];
__device__ int    g_bpref[SCAN_NB];

// ---------------- prep kernels ----------------
__global__ void k_count_deg(const int* __restrict__ dst, int e) {
    int i = blockIdx.x * blockDim.x + threadIdx.x;
    if (i < e) atomicAdd(&g_cnt[dst[i]], 1);
}
// scan1 + dinv fused: partial inclusive scan of cnt, plus dinv = rsqrt(cnt+1)
__global__ void k_scan1(int n) {
    __shared__ int sh[SCAN_BS];
    int i = blockIdx.x * SCAN_BS + threadIdx.x;
    int c = (i < n) ? g_cnt[i] : 0;
    if (i < n) g_dinv[i] = rsqrtf((float)(c + 1));
    sh[threadIdx.x] = c;
    __syncthreads();
    for (int ofs = 1; ofs < SCAN_BS; ofs <<= 1) {
        int t = (threadIdx.x >= ofs) ? sh[threadIdx.x - ofs] : 0;
        __syncthreads();
        sh[threadIdx.x] += t;
        __syncthreads();
    }
    if (i < n) g_cur[i] = sh[threadIdx.x];
    if (threadIdx.x == SCAN_BS - 1) g_bsum[blockIdx.x] = sh[SCAN_BS - 1];
}
// parallel exclusive scan of block sums (nb <= 128), one block of 128 threads
__global__ void k_scan2(int nb) {
    __shared__ int wsum[4];
    int t = threadIdx.x;
    int lane = t & 31, w = t >> 5;
    int v = (t < nb) ? g_bsum[t] : 0;
    int inc = v;
#pragma unroll
    for (int ofs = 1; ofs < 32; ofs <<= 1) {
        int u = __shfl_up_sync(0xFFFFFFFF, inc, ofs);
        if (lane >= ofs) inc += u;
    }
    if (lane == 31) wsum[w] = inc;
    __syncthreads();
    int woff = 0;
#pragma unroll
    for (int j = 0; j < 4; ++j) woff += (j < w) ? wsum[j] : 0;
    if (t < nb) g_bpref[t] = woff + inc - v;   // exclusive
}
__global__ void k_scan3(int n) {
    int i = blockIdx.x * SCAN_BS + threadIdx.x;
    if (i >= n) return;
    int inc = g_cur[i] + g_bpref[blockIdx.x];
    int ex = inc - g_cnt[i];
    g_off[i] = ex;
    g_cur[i] = ex;
    if (i == n - 1) g_off[n] = inc;
}
__global__ void k_scatter(const int* __restrict__ src, const int* __restrict__ dst, int e) {
    int i = blockIdx.x * blockDim.x + threadIdx.x;
    if (i >= e) return;
    int s = src[i], d = dst[i];
    int p = atomicAdd(&g_cur[d], 1);
    float nm = g_dinv[s] * g_dinv[d];
    g_edge[p] = make_int2(s, __float_as_int(nm));
}

// smem-tiled transpose+convert: Wt[n][k] = fp16(W[k][n]); W is 128x128
__global__ void k_transW(const float* __restrict__ W, __half* __restrict__ Wt) {
    __shared__ float tile[32][33];
    int bn = blockIdx.x * 32, bk = blockIdx.y * 32;
    int tx = threadIdx.x, ty = threadIdx.y;          // 32 x 8
#pragma unroll
    for (int r = 0; r < 32; r += 8)
        tile[ty + r][tx] = W[(size_t)(bk + ty + r) * 128 + bn + tx];
    __syncthreads();
#pragma unroll
    for (int r = 0; r < 32; r += 8)
        Wt[(size_t)(bn + ty + r) * 128 + bk + tx] = __float2half_rn(tile[tx][ty + r]);
}

// ---------------- fp16 mma.sync GEMM (+ optional fused 10-class head) ----------------
#define PADH 136
#define HPAD 129
// smem: max(gemm tiles, head tile + fW2 + fb2)
#define GEMM_SMEM_BYTES (2 * 128 * PADH * sizeof(__half))                    // 69632
#define HEAD_SMEM_BYTES ((128 * HPAD + 128 * N_CLASSES + N_CLASSES) * 4)     // 71208
#define SMEM_BYTES (HEAD_SMEM_BYTES > GEMM_SMEM_BYTES ? HEAD_SMEM_BYTES : GEMM_SMEM_BYTES)

__device__ __forceinline__ void mma_f16(float c[4], const uint32_t a[4],
                                        uint32_t b0, uint32_t b1) {
    asm volatile(
        "mma.sync.aligned.m16n8k16.row.col.f32.f16.f16.f32 "
        "{%0,%1,%2,%3}, {%4,%5,%6,%7}, {%8,%9}, {%0,%1,%2,%3};"
        : "+f"(c[0]), "+f"(c[1]), "+f"(c[2]), "+f"(c[3])
        : "r"(a[0]), "r"(a[1]), "r"(a[2]), "r"(a[3]), "r"(b0), "r"(b1));
}

// A input: fp16 (A16) or fp32 (A32, converted during staging).
// do_head: bias+relu tile -> smem fp32 -> out = tile @ W2 + b2 (to OutF).
// else: write fp16 tile to C16.
__global__ __launch_bounds__(256) void k_gemm_mma(
    const __half* __restrict__ A16, const float* __restrict__ A32,
    const __half* __restrict__ Wt, const float* __restrict__ bias,
    __half* __restrict__ C16,
    const float* __restrict__ W2, const float* __restrict__ b2,
    float* __restrict__ OutF,
    int M, int has_bias, int do_relu, int do_head)
{
    extern __shared__ __half smh[];
    __half* sA = smh;                  // [128][PADH]
    __half* sW = smh + 128 * PADH;     // [n][k]

    int tid = threadIdx.x;
    int wid = tid >> 5, lane = tid & 31;
    int gID = lane >> 2, tig = lane & 3;
    int row0 = blockIdx.x * 128;

    if (A32) {
#pragma unroll
        for (int i = 0; i < 16; ++i) {
            int fid = i * 256 + tid;
            int r = fid >> 5, c4 = (fid & 31) << 2;
            float4 v = make_float4(0.f, 0.f, 0.f, 0.f);
            int gr = row0 + r;
            if (gr < M) v = __ldg((const float4*)(A32 + (size_t)gr * 128 + c4));
            __half2 lo = __float22half2_rn(make_float2(v.x, v.y));
            __half2 hi = __float22half2_rn(make_float2(v.z, v.w));
            *(uint2*)(sA + r * PADH + c4) = make_uint2(*(uint32_t*)&lo, *(uint32_t*)&hi);
        }
    } else {
#pragma unroll
        for (int i = 0; i < 8; ++i) {
            int fid = i * 256 + tid;
            int r = fid >> 4, c8 = (fid & 15) << 3;
            uint4 v = make_uint4(0, 0, 0, 0);
            int gr = row0 + r;
            if (gr < M) v = __ldg((const uint4*)(A16 + (size_t)gr * 128 + c8));
            *(uint4*)(sA + r * PADH + c8) = v;
        }
    }
#pragma unroll
    for (int i = 0; i < 8; ++i) {
        int fid = i * 256 + tid;
        int n = fid >> 4, k8 = (fid & 15) << 3;
        uint4 v = __ldg((const uint4*)(Wt + (size_t)n * 128 + k8));
        *(uint4*)(sW + n * PADH + k8) = v;
    }
    __syncthreads();

    int wm = (wid & 3) * 32;
    int wn = (wid >> 2) * 64;

    float acc[2][8][4];
#pragma unroll
    for (int mf = 0; mf < 2; ++mf)
#pragma unroll
        for (int nf = 0; nf < 8; ++nf)
#pragma unroll
            for (int j = 0; j < 4; ++j) acc[mf][nf][j] = 0.f;

#pragma unroll
    for (int k0 = 0; k0 < 128; k0 += 16) {
        uint32_t a[2][4];
#pragma unroll
        for (int mf = 0; mf < 2; ++mf) {
            int mr = wm + mf * 16;
            a[mf][0] = *(const uint32_t*)(sA + (mr + gID)     * PADH + k0 + 2 * tig);
            a[mf][1] = *(const uint32_t*)(sA + (mr + gID + 8) * PADH + k0 + 2 * tig);
            a[mf][2] = *(const uint32_t*)(sA + (mr + gID)     * PADH + k0 + 2 * tig + 8);
            a[mf][3] = *(const uint32_t*)(sA + (mr + gID + 8) * PADH + k0 + 2 * tig + 8);
        }
#pragma unroll
        for (int nf = 0; nf < 8; ++nf) {
            int nc = wn + nf * 8;
            uint32_t b0 = *(const uint32_t*)(sW + (nc + gID) * PADH + k0 + 2 * tig);
            uint32_t b1 = *(const uint32_t*)(sW + (nc + gID) * PADH + k0 + 2 * tig + 8);
            mma_f16(acc[0][nf], a[0], b0, b1);
            mma_f16(acc[1][nf], a[1], b0, b1);
        }
    }

    if (!do_head) {
#pragma unroll
        for (int mf = 0; mf < 2; ++mf) {
            int r_lo = row0 + wm + mf * 16 + gID;
            int r_hi = r_lo + 8;
#pragma unroll
            for (int nf = 0; nf < 8; ++nf) {
                int col = wn + nf * 8 + tig * 2;
                float2 vlo = make_float2(acc[mf][nf][0], acc[mf][nf][1]);
                float2 vhi = make_float2(acc[mf][nf][2], acc[mf][nf][3]);
                if (has_bias) {
                    float bx = bias[col], by = bias[col + 1];
                    vlo.x += bx; vlo.y += by;
                    vhi.x += bx; vhi.y += by;
                }
                if (do_relu) {
                    vlo.x = fmaxf(vlo.x, 0.f); vlo.y = fmaxf(vlo.y, 0.f);
                    vhi.x = fmaxf(vhi.x, 0.f); vhi.y = fmaxf(vhi.y, 0.f);
                }
                if (r_lo < M) *(__half2*)(C16 + (size_t)r_lo * 128 + col) = __float22half2_rn(vlo);
                if (r_hi < M) *(__half2*)(C16 + (size_t)r_hi * 128 + col) = __float22half2_rn(vhi);
            }
        }
        return;
    }

    // ---- fused head path: tile -> smem fp32, then tile @ W2 + b2 ----
    __syncthreads();   // done with sA/sW
    float* sT  = (float*)smh;               // [128][HPAD]
    float* sW2 = sT + 128 * HPAD;           // [128][10]
    float* sb2 = sW2 + 128 * N_CLASSES;     // [10]

#pragma unroll
    for (int mf = 0; mf < 2; ++mf) {
        int lr_lo = wm + mf * 16 + gID;
        int lr_hi = lr_lo + 8;
#pragma unroll
        for (int nf = 0; nf < 8; ++nf) {
            int col = wn + nf * 8 + tig * 2;
            float bx = bias[col], by = bias[col + 1];
            sT[lr_lo * HPAD + col]     = fmaxf(acc[mf][nf][0] + bx, 0.f);
            sT[lr_lo * HPAD + col + 1] = fmaxf(acc[mf][nf][1] + by, 0.f);
            sT[lr_hi * HPAD + col]     = fmaxf(acc[mf][nf][2] + bx, 0.f);
            sT[lr_hi * HPAD + col + 1] = fmaxf(acc[mf][nf][3] + by, 0.f);
        }
    }
    for (int i = tid; i < 128 * N_CLASSES; i += 256) sW2[i] = __ldg(W2 + i);
    if (tid < N_CLASSES) sb2[tid] = b2[tid];
    __syncthreads();

    // 1280 outputs, 256 threads -> 5 each
    for (int o = tid; o < 128 * N_CLASSES; o += 256) {
        int r = o / N_CLASSES, c = o % N_CLASSES;
        int gr = row0 + r;
        if (gr >= M) continue;
        float s = sb2[c];
        const float* tr = sT + r * HPAD;
#pragma unroll
        for (int k = 0; k < 128; ++k)
            s = fmaf(tr[k], sW2[k * N_CLASSES + c], s);
        OutF[(size_t)gr * N_CLASSES + c] = s;
    }
}

// ---------------- CSR aggregation: one warp per node, 8-deep MLP, fp16 in/out ----------------
__global__ __launch_bounds__(256) void k_aggregate(
    const __half* __restrict__ h, const float* __restrict__ bias,
    __half* __restrict__ out, int N)
{
    int warp = (blockIdx.x << 3) + (threadIdx.x >> 5);
    if (warp >= N) return;
    int i = warp;
    int lane = threadIdx.x & 31;

    const __half* hcol = h + lane * 4;
    float4 acc = make_float4(0.f, 0.f, 0.f, 0.f);

    int e0 = g_off[i], e1 = g_off[i + 1];
    for (int e = e0; e < e1; e += 8) {
        int n = e1 - e;
        int2 rec[8];
        uint2 hv[8];
#pragma unroll
        for (int j = 0; j < 8; ++j)
            if (j < n) rec[j] = __ldg(&g_edge[e + j]);
#pragma unroll
        for (int j = 0; j < 8; ++j)
            if (j < n) hv[j] = __ldg((const uint2*)(hcol + (size_t)rec[j].x * 128));
#pragma unroll
        for (int j = 0; j < 8; ++j) {
            if (j < n) {
                float nm = __int_as_float(rec[j].y);
                float2 a = __half22float2(*(const __half2*)&hv[j].x);
                float2 b = __half22float2(*(const __half2*)&hv[j].y);
                acc.x = fmaf(nm, a.x, acc.x); acc.y = fmaf(nm, a.y, acc.y);
                acc.z = fmaf(nm, b.x, acc.z); acc.w = fmaf(nm, b.y, acc.w);
            }
        }
    }

    float di = g_dinv[i];
    float dii = di * di;
    uint2 us = __ldg((const uint2*)(hcol + (size_t)i * 128));
    float2 sa = __half22float2(*(const __half2*)&us.x);
    float2 sb = __half22float2(*(const __half2*)&us.y);
    float4 bv = __ldg((const float4*)(bias + lane * 4));
    acc.x = fmaxf(fmaf(dii, sa.x, acc.x) + bv.x, 0.f);
    acc.y = fmaxf(fmaf(dii, sa.y, acc.y) + bv.y, 0.f);
    acc.z = fmaxf(fmaf(dii, sb.x, acc.z) + bv.z, 0.f);
    acc.w = fmaxf(fmaf(dii, sb.y, acc.w) + bv.w, 0.f);

    __half2 lo = __float22half2_rn(make_float2(acc.x, acc.y));
    __half2 hi = __float22half2_rn(make_float2(acc.z, acc.w));
    *(uint2*)(out + (size_t)i * 128 + lane * 4) =
        make_uint2(*(uint32_t*)&lo, *(uint32_t*)&hi);
}

// ---------------- host launch ----------------
extern "C" void kernel_launch(void* const* d_in, const int* in_sizes, int n_in,
                              void* d_out, int out_size)
{
    const float* x   = (const float*)d_in[0];
    const int*   ei  = (const int*)d_in[1];
    const float* W1  = (const float*)d_in[2];
    const float* b1  = (const float*)d_in[3];
    const float* W2  = (const float*)d_in[4];
    const float* b2  = (const float*)d_in[5];
    const float* W3  = (const float*)d_in[6];
    const float* b3  = (const float*)d_in[7];
    const float* fW1 = (const float*)d_in[8];
    const float* fb1 = (const float*)d_in[9];
    const float* fW2 = (const float*)d_in[10];
    const float* fb2 = (const float*)d_in[11];
    float* out = (float*)d_out;

    int N = in_sizes[0] / DIM;
    int E = in_sizes[1] / 2;
    const int* src = ei;
    const int* dst = ei + E;

    __half *bufH, *bufP, *wt;
    int* cntp;
    cudaGetSymbolAddress((void**)&bufH, g_bufH);
    cudaGetSymbolAddress((void**)&bufP, g_bufP);
    cudaGetSymbolAddress((void**)&wt,   g_Wt);
    cudaGetSymbolAddress((void**)&cntp, g_cnt);
    __half* Wt1 = wt;
    __half* Wt2 = wt + DIM * DIM;
    __half* Wt3 = wt + 2 * DIM * DIM;
    __half* Wt4 = wt + 3 * DIM * DIM;

    cudaFuncSetAttribute(k_gemm_mma, cudaFuncAttributeMaxDynamicSharedMemorySize,
                         (int)SMEM_BYTES);

    int nb256_N = (N + 255) / 256;
    int nb256_E = (E + 255) / 256;
    int nbScan  = (N + SCAN_BS - 1) / SCAN_BS;
    int nbGemm  = (N + 127) / 128;
    int nbAgg   = (N + 7) / 8;

    // graph structure prep
    cudaMemsetAsync(cntp, 0, (size_t)N * sizeof(int));
    k_count_deg<<<nb256_E, 256>>>(dst, E);
    k_scan1<<<nbScan, SCAN_BS>>>(N);
    k_scan2<<<1, 128>>>(nbScan);
    k_scan3<<<nbScan, SCAN_BS>>>(N);
    k_scatter<<<nb256_E, 256>>>(src, dst, E);

    // weight pre-transpose (fp16)
    dim3 trGrid(4, 4), trBlk(32, 8);
    k_transW<<<trGrid, trBlk>>>(W1, Wt1);
    k_transW<<<trGrid, trBlk>>>(W2, Wt2);
    k_transW<<<trGrid, trBlk>>>(W3, Wt3);
    k_transW<<<trGrid, trBlk>>>(fW1, Wt4);

    // layer 1 (A from fp32 x, converted in staging)
    k_gemm_mma<<<nbGemm, 256, SMEM_BYTES>>>(nullptr, x, Wt1, nullptr, bufH,
                                            nullptr, nullptr, nullptr, N, 0, 0, 0);
    k_aggregate<<<nbAgg, 256>>>(bufH, b1, bufP, N);
    // layer 2
    k_gemm_mma<<<nbGemm, 256, SMEM_BYTES>>>(bufP, nullptr, Wt2, nullptr, bufH,
                                            nullptr, nullptr, nullptr, N, 0, 0, 0);
    k_aggregate<<<nbAgg, 256>>>(bufH, b2, bufP, N);
    // layer 3
    k_gemm_mma<<<nbGemm, 256, SMEM_BYTES>>>(bufP, nullptr, Wt3, nullptr, bufH,
                                            nullptr, nullptr, nullptr, N, 0, 0, 0);
    k_aggregate<<<nbAgg, 256>>>(bufH, b3, bufP, N);
    // FFN + fused head
    k_gemm_mma<<<nbGemm, 256, SMEM_BYTES>>>(bufP, nullptr, Wt4, fb1, nullptr,
                                            fW2, fb2, out, N, 1, 1, 1);
}